// round 3
// baseline (speedup 1.0000x reference)
#include <cuda_runtime.h>
#include <math.h>

#define DIMC 1024
#define NH   16
#define HD   64
#define BB   4
#define TT   2048
#define MTOT (BB*TT)   /* 8192 */

// Scratch (device globals — no allocations allowed)
__device__ float g_q  [(size_t)MTOT*DIMC];
__device__ float g_k  [(size_t)MTOT*DIMC];
__device__ float g_v  [(size_t)MTOT*DIMC];
__device__ float g_att[(size_t)MTOT*DIMC];

// ---------------------------------------------------------------------------
// C[M,N] = A[M,K] @ W[N,K]^T (+ optional bias[N])   — torch Linear semantics
// 64x64 tile, BK=16, 256 threads, 4x4 per thread, fp32.
// Global loads software-pipelined one K-step ahead (register staging).
// ---------------------------------------------------------------------------
__global__ __launch_bounds__(256) void gemm_nt(
    const float* __restrict__ A, const float* __restrict__ W,
    const float* __restrict__ bias, float* __restrict__ C,
    int M, int N, int K)
{
    __shared__ float As[16][68];   // [k][m]
    __shared__ float Ws[16][68];   // [k][n]
    const int bm = blockIdx.y * 64, bn = blockIdx.x * 64;
    const int tid = threadIdx.x;
    const int tx = tid & 15, ty = tid >> 4;
    const int lr = tid >> 2;          // 0..63
    const int lc = (tid & 3) * 4;     // 0,4,8,12

    float acc[4][4] = {};
    const float* Arow = A + (size_t)(bm + lr) * K + lc;
    const float* Wrow = W + (size_t)(bn + lr) * K + lc;

    // prefetch k0 = 0
    float4 a4 = *(const float4*)(Arow);
    float4 w4 = *(const float4*)(Wrow);

    for (int k0 = 0; k0 < K; k0 += 16) {
        As[lc+0][lr] = a4.x; As[lc+1][lr] = a4.y; As[lc+2][lr] = a4.z; As[lc+3][lr] = a4.w;
        Ws[lc+0][lr] = w4.x; Ws[lc+1][lr] = w4.y; Ws[lc+2][lr] = w4.z; Ws[lc+3][lr] = w4.w;
        __syncthreads();

        // prefetch next K-step while the FMA block runs
        if (k0 + 16 < K) {
            a4 = *(const float4*)(Arow + k0 + 16);
            w4 = *(const float4*)(Wrow + k0 + 16);
        }

        #pragma unroll
        for (int kk = 0; kk < 16; kk++) {
            float4 av = *(const float4*)&As[kk][ty*4];
            float4 bv = *(const float4*)&Ws[kk][tx*4];
            float a[4] = {av.x, av.y, av.z, av.w};
            float b[4] = {bv.x, bv.y, bv.z, bv.w};
            #pragma unroll
            for (int i = 0; i < 4; i++)
                #pragma unroll
                for (int j = 0; j < 4; j++)
                    acc[i][j] = fmaf(a[i], b[j], acc[i][j]);
        }
        __syncthreads();
    }

    #pragma unroll
    for (int i = 0; i < 4; i++) {
        const int r = bm + ty*4 + i;
        #pragma unroll
        for (int j = 0; j < 4; j++) {
            const int c = bn + tx*4 + j;
            float v = acc[i][j];
            if (bias) v += bias[c];
            C[(size_t)r * N + c] = v;
        }
    }
}

// ---------------------------------------------------------------------------
// Causal flash attention, one block per (q-tile of 64, head, batch).
// Tiles 64x64, head_dim = 64, online softmax, fp32.
// smem: Qs,Ks,Vs,Ps each [64][68] -> 69632 B dynamic.
// ---------------------------------------------------------------------------
#define ATT_SMEM (4 * 64 * 68 * 4)

__global__ __launch_bounds__(256) void attn_kernel(float* __restrict__ out)
{
    extern __shared__ float sm[];
    float* Qs = sm;               // [64][68]
    float* Ks = sm + 64*68;
    float* Vs = sm + 2*64*68;
    float* Ps = sm + 3*64*68;

    const int qt = blockIdx.x, h = blockIdx.y, b = blockIdx.z;
    const int tid = threadIdx.x;
    const int tx = tid & 15, ty = tid >> 4;
    const float scale = 0.125f;   // 1/sqrt(64)

    const size_t base = ((size_t)b * TT) * DIMC + (size_t)h * HD;

    // Load Q tile (coalesced float4)
    #pragma unroll
    for (int i = 0; i < 4; i++) {
        int idx = tid + i * 256;            // 0..1023 float4s
        int r = idx >> 4, c4 = idx & 15;
        *(float4*)&Qs[r*68 + c4*4] =
            *(const float4*)&g_q[base + (size_t)(qt*64 + r) * DIMC + c4*4];
    }

    float m[4], l[4], acc[4][4];
    #pragma unroll
    for (int i = 0; i < 4; i++) {
        m[i] = -1e30f; l[i] = 0.f;
        #pragma unroll
        for (int j = 0; j < 4; j++) acc[i][j] = 0.f;
    }
    __syncthreads();

    for (int kt = 0; kt <= qt; kt++) {
        // Load K,V tiles
        #pragma unroll
        for (int i = 0; i < 4; i++) {
            int idx = tid + i * 256;
            int r = idx >> 4, c4 = idx & 15;
            size_t g = base + (size_t)(kt*64 + r) * DIMC + c4*4;
            *(float4*)&Ks[r*68 + c4*4] = *(const float4*)&g_k[g];
            *(float4*)&Vs[r*68 + c4*4] = *(const float4*)&g_v[g];
        }
        __syncthreads();

        // S = Q @ K^T (4x4 per thread over full hd=64)
        float s[4][4] = {};
        #pragma unroll
        for (int d4 = 0; d4 < 16; d4++) {
            float4 q[4], k[4];
            #pragma unroll
            for (int i = 0; i < 4; i++) q[i] = *(const float4*)&Qs[(ty*4+i)*68 + d4*4];
            #pragma unroll
            for (int j = 0; j < 4; j++) k[j] = *(const float4*)&Ks[(tx*4+j)*68 + d4*4];
            #pragma unroll
            for (int i = 0; i < 4; i++)
                #pragma unroll
                for (int j = 0; j < 4; j++) {
                    s[i][j] = fmaf(q[i].x, k[j].x, s[i][j]);
                    s[i][j] = fmaf(q[i].y, k[j].y, s[i][j]);
                    s[i][j] = fmaf(q[i].z, k[j].z, s[i][j]);
                    s[i][j] = fmaf(q[i].w, k[j].w, s[i][j]);
                }
        }

        const bool diag = (kt == qt);
        float tmax[4];
        #pragma unroll
        for (int i = 0; i < 4; i++) {
            const int qi = ty*4 + i;          // relative row in tile
            float mx = -1e30f;
            #pragma unroll
            for (int j = 0; j < 4; j++) {
                float v = s[i][j] * scale;
                if (diag && (tx*4 + j > qi)) v = -1e30f;
                s[i][j] = v;
                mx = fmaxf(mx, v);
            }
            tmax[i] = mx;
        }
        // row max across 16-lane tx group
        #pragma unroll
        for (int i = 0; i < 4; i++) {
            float v = tmax[i];
            v = fmaxf(v, __shfl_xor_sync(0xffffffffu, v, 1));
            v = fmaxf(v, __shfl_xor_sync(0xffffffffu, v, 2));
            v = fmaxf(v, __shfl_xor_sync(0xffffffffu, v, 4));
            v = fmaxf(v, __shfl_xor_sync(0xffffffffu, v, 8));
            tmax[i] = v;
        }
        // online softmax update
        #pragma unroll
        for (int i = 0; i < 4; i++) {
            float mn   = fmaxf(m[i], tmax[i]);
            float corr = __expf(m[i] - mn);
            m[i] = mn;
            float rs = 0.f;
            #pragma unroll
            for (int j = 0; j < 4; j++) {
                float p = __expf(s[i][j] - mn);
                s[i][j] = p;
                rs += p;
            }
            rs += __shfl_xor_sync(0xffffffffu, rs, 1);
            rs += __shfl_xor_sync(0xffffffffu, rs, 2);
            rs += __shfl_xor_sync(0xffffffffu, rs, 4);
            rs += __shfl_xor_sync(0xffffffffu, rs, 8);
            l[i] = l[i] * corr + rs;
            #pragma unroll
            for (int j = 0; j < 4; j++) acc[i][j] *= corr;
        }

        // stage P in smem
        #pragma unroll
        for (int i = 0; i < 4; i++)
            *(float4*)&Ps[(ty*4+i)*68 + tx*4] =
                make_float4(s[i][0], s[i][1], s[i][2], s[i][3]);
        __syncthreads();

        // acc += P @ V
        #pragma unroll 8
        for (int kk = 0; kk < 64; kk++) {
            float4 v4 = *(const float4*)&Vs[kk*68 + tx*4];
            float p0 = Ps[(ty*4+0)*68 + kk];
            float p1 = Ps[(ty*4+1)*68 + kk];
            float p2 = Ps[(ty*4+2)*68 + kk];
            float p3 = Ps[(ty*4+3)*68 + kk];
            acc[0][0] = fmaf(p0, v4.x, acc[0][0]); acc[0][1] = fmaf(p0, v4.y, acc[0][1]);
            acc[0][2] = fmaf(p0, v4.z, acc[0][2]); acc[0][3] = fmaf(p0, v4.w, acc[0][3]);
            acc[1][0] = fmaf(p1, v4.x, acc[1][0]); acc[1][1] = fmaf(p1, v4.y, acc[1][1]);
            acc[1][2] = fmaf(p1, v4.z, acc[1][2]); acc[1][3] = fmaf(p1, v4.w, acc[1][3]);
            acc[2][0] = fmaf(p2, v4.x, acc[2][0]); acc[2][1] = fmaf(p2, v4.y, acc[2][1]);
            acc[2][2] = fmaf(p2, v4.z, acc[2][2]); acc[2][3] = fmaf(p2, v4.w, acc[2][3]);
            acc[3][0] = fmaf(p3, v4.x, acc[3][0]); acc[3][1] = fmaf(p3, v4.y, acc[3][1]);
            acc[3][2] = fmaf(p3, v4.z, acc[3][2]); acc[3][3] = fmaf(p3, v4.w, acc[3][3]);
        }
        __syncthreads();
    }

    // normalize + write
    #pragma unroll
    for (int i = 0; i < 4; i++) {
        float inv = 1.0f / l[i];
        size_t r = (size_t)qt*64 + ty*4 + i;
        *(float4*)&out[base + r * DIMC + tx*4] =
            make_float4(acc[i][0]*inv, acc[i][1]*inv, acc[i][2]*inv, acc[i][3]*inv);
    }
}

// ---------------------------------------------------------------------------
extern "C" void kernel_launch(void* const* d_in, const int* in_sizes, int n_in,
                              void* d_out, int out_size)
{
    const float* x  = (const float*)d_in[0];
    // d_in[1] = mask (bool tril) — causal structure is computed analytically
    const float* Wq = (const float*)d_in[2];
    const float* Wk = (const float*)d_in[3];
    const float* Wv = (const float*)d_in[4];
    const float* Wo = (const float*)d_in[5];
    const float* bo = (const float*)d_in[6];
    // d_in[7] = start_pos (0) — ignored
    float* out = (float*)d_out;

    float *q, *k, *v, *att;
    cudaGetSymbolAddress((void**)&q,   g_q);
    cudaGetSymbolAddress((void**)&k,   g_k);
    cudaGetSymbolAddress((void**)&v,   g_v);
    cudaGetSymbolAddress((void**)&att, g_att);

    cudaFuncSetAttribute(attn_kernel,
                         cudaFuncAttributeMaxDynamicSharedMemorySize, ATT_SMEM);

    dim3 gb(DIMC/64, MTOT/64);   // (16,128)
    gemm_nt<<<gb, 256>>>(x,   Wq, nullptr, q,   MTOT, DIMC, DIMC);
    gemm_nt<<<gb, 256>>>(x,   Wk, nullptr, k,   MTOT, DIMC, DIMC);
    gemm_nt<<<gb, 256>>>(x,   Wv, nullptr, v,   MTOT, DIMC, DIMC);

    dim3 ga(TT/64, NH, BB);      // (32,16,4)
    attn_kernel<<<ga, 256, ATT_SMEM>>>(att);

    gemm_nt<<<gb, 256>>>(att, Wo, bo, out, MTOT, DIMC, DIMC);
}

// round 8
// speedup vs baseline: 1.2270x; 1.2270x over previous
#include <cuda_runtime.h>
#include <cstdint>
#include <math.h>

#define DIMC 1024
#define NH   16
#define HD   64
#define BB   4
#define TT   2048
#define MTOT (BB*TT)   /* 8192 */

// Scratch (device globals — no allocations allowed)
__device__ float g_q  [(size_t)MTOT*DIMC];
__device__ float g_k  [(size_t)MTOT*DIMC];
__device__ float g_v  [(size_t)MTOT*DIMC];
__device__ float g_att[(size_t)MTOT*DIMC];

__device__ __forceinline__ float tf32_rna(float x) {
    float y;
    asm("cvt.rna.tf32.f32 %0, %1;" : "=f"(y) : "f"(x));
    return y;
}

__device__ __forceinline__ void mma_tf32(float* d, const uint32_t* a,
                                         const uint32_t* b) {
    asm volatile(
        "mma.sync.aligned.m16n8k8.row.col.f32.tf32.tf32.f32 "
        "{%0,%1,%2,%3}, {%4,%5,%6,%7}, {%8,%9}, {%0,%1,%2,%3};"
        : "+f"(d[0]), "+f"(d[1]), "+f"(d[2]), "+f"(d[3])
        : "r"(a[0]), "r"(a[1]), "r"(a[2]), "r"(a[3]), "r"(b[0]), "r"(b[1]));
}

// ===========================================================================
// 3xTF32 mma.sync GEMM: C[M,N] = A[M,K] @ W[N,K]^T (+bias)
// M=8192, N=K=1024.  CTA tile 128x128, 8 warps (4M x 2N), warp tile 32x64.
// BK=32 stage; smem holds hi/lo split tiles, row stride 36 floats
// (conflict-free fragment loads, float4-aligned stores).
// Dyn smem: 4 * 128*36*4 = 73728 B.
// ===========================================================================
#define GEMM_SMEM (4 * 128 * 36 * 4)

__global__ __launch_bounds__(256) void gemm_mma(
    const float* __restrict__ A, const float* __restrict__ W,
    const float* __restrict__ bias, float* __restrict__ C)
{
    extern __shared__ float sm[];
    float* s_ah = sm;                 // [128][36]
    float* s_al = sm + 128*36;
    float* s_wh = sm + 2*128*36;
    float* s_wl = sm + 3*128*36;

    const int tid  = threadIdx.x;
    const int wid  = tid >> 5, lane = tid & 31;
    const int wm   = (wid & 3) * 32;      // warp M offset in tile
    const int wn   = (wid >> 2) * 64;     // warp N offset in tile
    const int bm   = blockIdx.y * 128, bn = blockIdx.x * 128;

    const int lrow = tid >> 3;            // 0..31 (loader row within 32-row pass)
    const int lcol = (tid & 7) * 4;       // 0,4,...,28

    const int qr = lane >> 2;             // 0..7
    const int qc = lane & 3;              // 0..3

    float acc[2][8][4];
    #pragma unroll
    for (int i = 0; i < 2; i++)
        #pragma unroll
        for (int j = 0; j < 8; j++)
            #pragma unroll
            for (int t = 0; t < 4; t++) acc[i][j][t] = 0.f;

    // prefetch stage 0
    float4 pa[4], pw[4];
    #pragma unroll
    for (int p = 0; p < 4; p++) {
        pa[p] = *(const float4*)&A[(size_t)(bm + lrow + 32*p) * DIMC + lcol];
        pw[p] = *(const float4*)&W[(size_t)(bn + lrow + 32*p) * DIMC + lcol];
    }

    for (int k0 = 0; k0 < DIMC; k0 += 32) {
        // split & store stage (previous compute finished at loop-end sync)
        #pragma unroll
        for (int p = 0; p < 4; p++) {
            const int r = lrow + 32*p;
            float4 a = pa[p], w = pw[p];
            float4 ah, al, wh, wl;
            ah.x = tf32_rna(a.x); al.x = tf32_rna(a.x - ah.x);
            ah.y = tf32_rna(a.y); al.y = tf32_rna(a.y - ah.y);
            ah.z = tf32_rna(a.z); al.z = tf32_rna(a.z - ah.z);
            ah.w = tf32_rna(a.w); al.w = tf32_rna(a.w - ah.w);
            wh.x = tf32_rna(w.x); wl.x = tf32_rna(w.x - wh.x);
            wh.y = tf32_rna(w.y); wl.y = tf32_rna(w.y - wh.y);
            wh.z = tf32_rna(w.z); wl.z = tf32_rna(w.z - wh.z);
            wh.w = tf32_rna(w.w); wl.w = tf32_rna(w.w - wh.w);
            *(float4*)&s_ah[r*36 + lcol] = ah;
            *(float4*)&s_al[r*36 + lcol] = al;
            *(float4*)&s_wh[r*36 + lcol] = wh;
            *(float4*)&s_wl[r*36 + lcol] = wl;
        }
        __syncthreads();

        // prefetch next stage (overlaps with MMA block)
        if (k0 + 32 < DIMC) {
            #pragma unroll
            for (int p = 0; p < 4; p++) {
                pa[p] = *(const float4*)&A[(size_t)(bm + lrow + 32*p) * DIMC + k0 + 32 + lcol];
                pw[p] = *(const float4*)&W[(size_t)(bn + lrow + 32*p) * DIMC + k0 + 32 + lcol];
            }
        }

        #pragma unroll
        for (int k8 = 0; k8 < 4; k8++) {
            const int kk = k8*8 + qc;
            uint32_t ah[2][4], al[2][4], bh[8][2], bl[8][2];
            #pragma unroll
            for (int mf = 0; mf < 2; mf++) {
                const int m = wm + mf*16 + qr;
                ah[mf][0] = __float_as_uint(s_ah[m*36 + kk]);
                ah[mf][1] = __float_as_uint(s_ah[(m+8)*36 + kk]);
                ah[mf][2] = __float_as_uint(s_ah[m*36 + kk + 4]);
                ah[mf][3] = __float_as_uint(s_ah[(m+8)*36 + kk + 4]);
                al[mf][0] = __float_as_uint(s_al[m*36 + kk]);
                al[mf][1] = __float_as_uint(s_al[(m+8)*36 + kk]);
                al[mf][2] = __float_as_uint(s_al[m*36 + kk + 4]);
                al[mf][3] = __float_as_uint(s_al[(m+8)*36 + kk + 4]);
            }
            #pragma unroll
            for (int nf = 0; nf < 8; nf++) {
                const int n = wn + nf*8 + qr;
                bh[nf][0] = __float_as_uint(s_wh[n*36 + kk]);
                bh[nf][1] = __float_as_uint(s_wh[n*36 + kk + 4]);
                bl[nf][0] = __float_as_uint(s_wl[n*36 + kk]);
                bl[nf][1] = __float_as_uint(s_wl[n*36 + kk + 4]);
            }
            #pragma unroll
            for (int mf = 0; mf < 2; mf++)
                #pragma unroll
                for (int nf = 0; nf < 8; nf++) {
                    mma_tf32(acc[mf][nf], ah[mf], bh[nf]);   // hi*hi
                    mma_tf32(acc[mf][nf], al[mf], bh[nf]);   // lo*hi
                    mma_tf32(acc[mf][nf], ah[mf], bl[nf]);   // hi*lo
                }
        }
        __syncthreads();
    }

    // epilogue: c0,c1 at (row, col..col+1); c2,c3 at (row+8, ...)
    #pragma unroll
    for (int mf = 0; mf < 2; mf++) {
        const int row = bm + wm + mf*16 + qr;
        #pragma unroll
        for (int nf = 0; nf < 8; nf++) {
            const int col = bn + wn + nf*8 + qc*2;
            float2 v0 = make_float2(acc[mf][nf][0], acc[mf][nf][1]);
            float2 v1 = make_float2(acc[mf][nf][2], acc[mf][nf][3]);
            if (bias) {
                const float b0 = bias[col], b1 = bias[col+1];
                v0.x += b0; v0.y += b1;
                v1.x += b0; v1.y += b1;
            }
            *(float2*)&C[(size_t)row     * DIMC + col] = v0;
            *(float2*)&C[(size_t)(row+8) * DIMC + col] = v1;
        }
    }
}

// ---------------------------------------------------------------------------
// Causal flash attention (unchanged from passing round-3 kernel).
// ---------------------------------------------------------------------------
#define ATT_SMEM (4 * 64 * 68 * 4)

__global__ __launch_bounds__(256) void attn_kernel(float* __restrict__ out)
{
    extern __shared__ float sm[];
    float* Qs = sm;               // [64][68]
    float* Ks = sm + 64*68;
    float* Vs = sm + 2*64*68;
    float* Ps = sm + 3*64*68;

    const int qt = blockIdx.x, h = blockIdx.y, b = blockIdx.z;
    const int tid = threadIdx.x;
    const int tx = tid & 15, ty = tid >> 4;
    const float scale = 0.125f;   // 1/sqrt(64)

    const size_t base = ((size_t)b * TT) * DIMC + (size_t)h * HD;

    #pragma unroll
    for (int i = 0; i < 4; i++) {
        int idx = tid + i * 256;
        int r = idx >> 4, c4 = idx & 15;
        *(float4*)&Qs[r*68 + c4*4] =
            *(const float4*)&g_q[base + (size_t)(qt*64 + r) * DIMC + c4*4];
    }

    float m[4], l[4], acc[4][4];
    #pragma unroll
    for (int i = 0; i < 4; i++) {
        m[i] = -1e30f; l[i] = 0.f;
        #pragma unroll
        for (int j = 0; j < 4; j++) acc[i][j] = 0.f;
    }
    __syncthreads();

    for (int kt = 0; kt <= qt; kt++) {
        #pragma unroll
        for (int i = 0; i < 4; i++) {
            int idx = tid + i * 256;
            int r = idx >> 4, c4 = idx & 15;
            size_t g = base + (size_t)(kt*64 + r) * DIMC + c4*4;
            *(float4*)&Ks[r*68 + c4*4] = *(const float4*)&g_k[g];
            *(float4*)&Vs[r*68 + c4*4] = *(const float4*)&g_v[g];
        }
        __syncthreads();

        float s[4][4] = {};
        #pragma unroll
        for (int d4 = 0; d4 < 16; d4++) {
            float4 q[4], k[4];
            #pragma unroll
            for (int i = 0; i < 4; i++) q[i] = *(const float4*)&Qs[(ty*4+i)*68 + d4*4];
            #pragma unroll
            for (int j = 0; j < 4; j++) k[j] = *(const float4*)&Ks[(tx*4+j)*68 + d4*4];
            #pragma unroll
            for (int i = 0; i < 4; i++)
                #pragma unroll
                for (int j = 0; j < 4; j++) {
                    s[i][j] = fmaf(q[i].x, k[j].x, s[i][j]);
                    s[i][j] = fmaf(q[i].y, k[j].y, s[i][j]);
                    s[i][j] = fmaf(q[i].z, k[j].z, s[i][j]);
                    s[i][j] = fmaf(q[i].w, k[j].w, s[i][j]);
                }
        }

        const bool diag = (kt == qt);
        float tmax[4];
        #pragma unroll
        for (int i = 0; i < 4; i++) {
            const int qi = ty*4 + i;
            float mx = -1e30f;
            #pragma unroll
            for (int j = 0; j < 4; j++) {
                float v = s[i][j] * scale;
                if (diag && (tx*4 + j > qi)) v = -1e30f;
                s[i][j] = v;
                mx = fmaxf(mx, v);
            }
            tmax[i] = mx;
        }
        #pragma unroll
        for (int i = 0; i < 4; i++) {
            float v = tmax[i];
            v = fmaxf(v, __shfl_xor_sync(0xffffffffu, v, 1));
            v = fmaxf(v, __shfl_xor_sync(0xffffffffu, v, 2));
            v = fmaxf(v, __shfl_xor_sync(0xffffffffu, v, 4));
            v = fmaxf(v, __shfl_xor_sync(0xffffffffu, v, 8));
            tmax[i] = v;
        }
        #pragma unroll
        for (int i = 0; i < 4; i++) {
            float mn   = fmaxf(m[i], tmax[i]);
            float corr = __expf(m[i] - mn);
            m[i] = mn;
            float rs = 0.f;
            #pragma unroll
            for (int j = 0; j < 4; j++) {
                float p = __expf(s[i][j] - mn);
                s[i][j] = p;
                rs += p;
            }
            rs += __shfl_xor_sync(0xffffffffu, rs, 1);
            rs += __shfl_xor_sync(0xffffffffu, rs, 2);
            rs += __shfl_xor_sync(0xffffffffu, rs, 4);
            rs += __shfl_xor_sync(0xffffffffu, rs, 8);
            l[i] = l[i] * corr + rs;
            #pragma unroll
            for (int j = 0; j < 4; j++) acc[i][j] *= corr;
        }

        #pragma unroll
        for (int i = 0; i < 4; i++)
            *(float4*)&Ps[(ty*4+i)*68 + tx*4] =
                make_float4(s[i][0], s[i][1], s[i][2], s[i][3]);
        __syncthreads();

        #pragma unroll 8
        for (int kk = 0; kk < 64; kk++) {
            float4 v4 = *(const float4*)&Vs[kk*68 + tx*4];
            float p0 = Ps[(ty*4+0)*68 + kk];
            float p1 = Ps[(ty*4+1)*68 + kk];
            float p2 = Ps[(ty*4+2)*68 + kk];
            float p3 = Ps[(ty*4+3)*68 + kk];
            acc[0][0] = fmaf(p0, v4.x, acc[0][0]); acc[0][1] = fmaf(p0, v4.y, acc[0][1]);
            acc[0][2] = fmaf(p0, v4.z, acc[0][2]); acc[0][3] = fmaf(p0, v4.w, acc[0][3]);
            acc[1][0] = fmaf(p1, v4.x, acc[1][0]); acc[1][1] = fmaf(p1, v4.y, acc[1][1]);
            acc[1][2] = fmaf(p1, v4.z, acc[1][2]); acc[1][3] = fmaf(p1, v4.w, acc[1][3]);
            acc[2][0] = fmaf(p2, v4.x, acc[2][0]); acc[2][1] = fmaf(p2, v4.y, acc[2][1]);
            acc[2][2] = fmaf(p2, v4.z, acc[2][2]); acc[2][3] = fmaf(p2, v4.w, acc[2][3]);
            acc[3][0] = fmaf(p3, v4.x, acc[3][0]); acc[3][1] = fmaf(p3, v4.y, acc[3][1]);
            acc[3][2] = fmaf(p3, v4.z, acc[3][2]); acc[3][3] = fmaf(p3, v4.w, acc[3][3]);
        }
        __syncthreads();
    }

    #pragma unroll
    for (int i = 0; i < 4; i++) {
        float inv = 1.0f / l[i];
        size_t r = (size_t)qt*64 + ty*4 + i;
        *(float4*)&out[base + r * DIMC + tx*4] =
            make_float4(acc[i][0]*inv, acc[i][1]*inv, acc[i][2]*inv, acc[i][3]*inv);
    }
}

// ---------------------------------------------------------------------------
extern "C" void kernel_launch(void* const* d_in, const int* in_sizes, int n_in,
                              void* d_out, int out_size)
{
    const float* x  = (const float*)d_in[0];
    const float* Wq = (const float*)d_in[2];
    const float* Wk = (const float*)d_in[3];
    const float* Wv = (const float*)d_in[4];
    const float* Wo = (const float*)d_in[5];
    const float* bo = (const float*)d_in[6];
    float* out = (float*)d_out;

    float *q, *k, *v, *att;
    cudaGetSymbolAddress((void**)&q,   g_q);
    cudaGetSymbolAddress((void**)&k,   g_k);
    cudaGetSymbolAddress((void**)&v,   g_v);
    cudaGetSymbolAddress((void**)&att, g_att);

    cudaFuncSetAttribute(gemm_mma,
                         cudaFuncAttributeMaxDynamicSharedMemorySize, GEMM_SMEM);
    cudaFuncSetAttribute(attn_kernel,
                         cudaFuncAttributeMaxDynamicSharedMemorySize, ATT_SMEM);

    dim3 gb(DIMC/128, MTOT/128);   // (8, 64)
    gemm_mma<<<gb, 256, GEMM_SMEM>>>(x,   Wq, nullptr, q);
    gemm_mma<<<gb, 256, GEMM_SMEM>>>(x,   Wk, nullptr, k);
    gemm_mma<<<gb, 256, GEMM_SMEM>>>(x,   Wv, nullptr, v);

    dim3 ga(TT/64, NH, BB);        // (32,16,4)
    attn_kernel<<<ga, 256, ATT_SMEM>>>(att);

    gemm_mma<<<gb, 256, GEMM_SMEM>>>(att, Wo, bo, out);
}

// round 13
// speedup vs baseline: 1.6503x; 1.3450x over previous
#include <cuda_runtime.h>
#include <cstdint>
#include <math.h>

#define DIMC 1024
#define NH   16
#define HD   64
#define BB   4
#define TT   2048
#define MTOT (BB*TT)   /* 8192 */

// Scratch (device globals — no allocations allowed)
__device__ float g_q  [(size_t)MTOT*DIMC];
__device__ float g_k  [(size_t)MTOT*DIMC];
__device__ float g_v  [(size_t)MTOT*DIMC];
__device__ float g_att[(size_t)MTOT*DIMC];

__device__ __forceinline__ float tf32_rna(float x) {
    float y;
    asm("cvt.rna.tf32.f32 %0, %1;" : "=f"(y) : "f"(x));
    return y;
}

__device__ __forceinline__ void mma_tf32(float* d, const uint32_t* a,
                                         const uint32_t* b) {
    asm volatile(
        "mma.sync.aligned.m16n8k8.row.col.f32.tf32.tf32.f32 "
        "{%0,%1,%2,%3}, {%4,%5,%6,%7}, {%8,%9}, {%0,%1,%2,%3};"
        : "+f"(d[0]), "+f"(d[1]), "+f"(d[2]), "+f"(d[3])
        : "r"(a[0]), "r"(a[1]), "r"(a[2]), "r"(a[3]), "r"(b[0]), "r"(b[1]));
}

// Fast exp on the FMA pipe (MUFU rt=8/SMSP is the hidden softmax bottleneck).
// Valid for x <= ~0 (softmax args); clamps below -87. ~2e-6 rel error.
__device__ __forceinline__ float fast_exp(float x) {
    float z = fmaxf(x, -87.0f) * 1.4426950408889634f;   // log2(e)
    float r = z + 12582912.0f;                          // 2^23 + 2^22 magic
    int   n = __float_as_int(r) - 0x4B400000;
    float f = z - (r - 12582912.0f);                    // f in [-0.5, 0.5]
    float p = 0.0013333558f;
    p = fmaf(p, f, 0.0096181291f);
    p = fmaf(p, f, 0.0555041087f);
    p = fmaf(p, f, 0.2402265070f);
    p = fmaf(p, f, 0.6931471806f);
    p = fmaf(p, f, 1.0f);
    return p * __int_as_float((n + 127) << 23);
}

// ===========================================================================
// 3xTF32 mma.sync GEMM: C[M,N] = A[M,K] @ W[N,K]^T (+bias)  (validated R8)
// ===========================================================================
#define GEMM_SMEM (4 * 128 * 36 * 4)

__global__ __launch_bounds__(256) void gemm_mma(
    const float* __restrict__ A, const float* __restrict__ W,
    const float* __restrict__ bias, float* __restrict__ C)
{
    extern __shared__ float sm[];
    float* s_ah = sm;                 // [128][36]
    float* s_al = sm + 128*36;
    float* s_wh = sm + 2*128*36;
    float* s_wl = sm + 3*128*36;

    const int tid  = threadIdx.x;
    const int wid  = tid >> 5, lane = tid & 31;
    const int wm   = (wid & 3) * 32;
    const int wn   = (wid >> 2) * 64;
    const int bm   = blockIdx.y * 128, bn = blockIdx.x * 128;

    const int lrow = tid >> 3;
    const int lcol = (tid & 7) * 4;

    const int qr = lane >> 2;
    const int qc = lane & 3;

    float acc[2][8][4];
    #pragma unroll
    for (int i = 0; i < 2; i++)
        #pragma unroll
        for (int j = 0; j < 8; j++)
            #pragma unroll
            for (int t = 0; t < 4; t++) acc[i][j][t] = 0.f;

    float4 pa[4], pw[4];
    #pragma unroll
    for (int p = 0; p < 4; p++) {
        pa[p] = *(const float4*)&A[(size_t)(bm + lrow + 32*p) * DIMC + lcol];
        pw[p] = *(const float4*)&W[(size_t)(bn + lrow + 32*p) * DIMC + lcol];
    }

    for (int k0 = 0; k0 < DIMC; k0 += 32) {
        #pragma unroll
        for (int p = 0; p < 4; p++) {
            const int r = lrow + 32*p;
            float4 a = pa[p], w = pw[p];
            float4 ah, al, wh, wl;
            ah.x = tf32_rna(a.x); al.x = tf32_rna(a.x - ah.x);
            ah.y = tf32_rna(a.y); al.y = tf32_rna(a.y - ah.y);
            ah.z = tf32_rna(a.z); al.z = tf32_rna(a.z - ah.z);
            ah.w = tf32_rna(a.w); al.w = tf32_rna(a.w - ah.w);
            wh.x = tf32_rna(w.x); wl.x = tf32_rna(w.x - wh.x);
            wh.y = tf32_rna(w.y); wl.y = tf32_rna(w.y - wh.y);
            wh.z = tf32_rna(w.z); wl.z = tf32_rna(w.z - wh.z);
            wh.w = tf32_rna(w.w); wl.w = tf32_rna(w.w - wh.w);
            *(float4*)&s_ah[r*36 + lcol] = ah;
            *(float4*)&s_al[r*36 + lcol] = al;
            *(float4*)&s_wh[r*36 + lcol] = wh;
            *(float4*)&s_wl[r*36 + lcol] = wl;
        }
        __syncthreads();

        if (k0 + 32 < DIMC) {
            #pragma unroll
            for (int p = 0; p < 4; p++) {
                pa[p] = *(const float4*)&A[(size_t)(bm + lrow + 32*p) * DIMC + k0 + 32 + lcol];
                pw[p] = *(const float4*)&W[(size_t)(bn + lrow + 32*p) * DIMC + k0 + 32 + lcol];
            }
        }

        #pragma unroll
        for (int k8 = 0; k8 < 4; k8++) {
            const int kk = k8*8 + qc;
            uint32_t ah[2][4], al[2][4], bh[8][2], bl[8][2];
            #pragma unroll
            for (int mf = 0; mf < 2; mf++) {
                const int m = wm + mf*16 + qr;
                ah[mf][0] = __float_as_uint(s_ah[m*36 + kk]);
                ah[mf][1] = __float_as_uint(s_ah[(m+8)*36 + kk]);
                ah[mf][2] = __float_as_uint(s_ah[m*36 + kk + 4]);
                ah[mf][3] = __float_as_uint(s_ah[(m+8)*36 + kk + 4]);
                al[mf][0] = __float_as_uint(s_al[m*36 + kk]);
                al[mf][1] = __float_as_uint(s_al[(m+8)*36 + kk]);
                al[mf][2] = __float_as_uint(s_al[m*36 + kk + 4]);
                al[mf][3] = __float_as_uint(s_al[(m+8)*36 + kk + 4]);
            }
            #pragma unroll
            for (int nf = 0; nf < 8; nf++) {
                const int n = wn + nf*8 + qr;
                bh[nf][0] = __float_as_uint(s_wh[n*36 + kk]);
                bh[nf][1] = __float_as_uint(s_wh[n*36 + kk + 4]);
                bl[nf][0] = __float_as_uint(s_wl[n*36 + kk]);
                bl[nf][1] = __float_as_uint(s_wl[n*36 + kk + 4]);
            }
            #pragma unroll
            for (int mf = 0; mf < 2; mf++)
                #pragma unroll
                for (int nf = 0; nf < 8; nf++) {
                    mma_tf32(acc[mf][nf], ah[mf], bh[nf]);
                    mma_tf32(acc[mf][nf], al[mf], bh[nf]);
                    mma_tf32(acc[mf][nf], ah[mf], bl[nf]);
                }
        }
        __syncthreads();
    }

    #pragma unroll
    for (int mf = 0; mf < 2; mf++) {
        const int row = bm + wm + mf*16 + qr;
        #pragma unroll
        for (int nf = 0; nf < 8; nf++) {
            const int col = bn + wn + nf*8 + qc*2;
            float2 v0 = make_float2(acc[mf][nf][0], acc[mf][nf][1]);
            float2 v1 = make_float2(acc[mf][nf][2], acc[mf][nf][3]);
            if (bias) {
                const float b0 = bias[col], b1 = bias[col+1];
                v0.x += b0; v0.y += b1;
                v1.x += b0; v1.y += b1;
            }
            *(float2*)&C[(size_t)row     * DIMC + col] = v0;
            *(float2*)&C[(size_t)(row+8) * DIMC + col] = v1;
        }
    }
}

// ===========================================================================
// Tensor-core causal flash attention, 3xTF32.
// Block = 128 q-rows x (head, batch). 8 warps, warp owns 16 rows.
// K-tiles of 64. Strides: Q/K/P 68 (banks 4*qr+qc), V 72 (banks 8*qc+qr).
// ===========================================================================
#define AQ 68
#define AK 68
#define AV 72
#define AP 68
#define OFF_QH 0
#define OFF_QL (128*AQ)
#define OFF_KH (2*128*AQ)
#define OFF_KL (OFF_KH + 64*AK)
#define OFF_VH (OFF_KL + 64*AK)
#define OFF_VL (OFF_VH + 64*AV)
#define OFF_PH (OFF_VL + 64*AV)
#define OFF_PL (OFF_PH + 128*AP)
#define ATT_SMEM ((OFF_PL + 128*AP) * 4)   /* 210944 B */

__global__ __launch_bounds__(256) void attn_mma(float* __restrict__ out)
{
    extern __shared__ float sm[];
    const int tid  = threadIdx.x;
    const int w    = tid >> 5, lane = tid & 31;
    const int qr   = lane >> 2, qc = lane & 3;
    const int qt   = blockIdx.x, h = blockIdx.y, b = blockIdx.z;
    const size_t base = ((size_t)b * TT) * DIMC + (size_t)h * HD;

    // ---- load Q tile (128x64), fold scale 1/8 (exact pow2), split hi/lo ----
    #pragma unroll
    for (int i = 0; i < 8; i++) {
        int idx = tid + i * 256;           // 0..2047
        int r = idx >> 4, c = (idx & 15) * 4;
        float4 v = *(const float4*)&g_q[base + (size_t)(qt*128 + r) * DIMC + c];
        v.x *= 0.125f; v.y *= 0.125f; v.z *= 0.125f; v.w *= 0.125f;
        float4 hi, lo;
        hi.x = tf32_rna(v.x); lo.x = tf32_rna(v.x - hi.x);
        hi.y = tf32_rna(v.y); lo.y = tf32_rna(v.y - hi.y);
        hi.z = tf32_rna(v.z); lo.z = tf32_rna(v.z - hi.z);
        hi.w = tf32_rna(v.w); lo.w = tf32_rna(v.w - hi.w);
        *(float4*)&sm[OFF_QH + r*AQ + c] = hi;
        *(float4*)&sm[OFF_QL + r*AQ + c] = lo;
    }

    float m0 = -1e30f, m1 = -1e30f, l0 = 0.f, l1 = 0.f;
    float oacc[8][4];
    #pragma unroll
    for (int nf = 0; nf < 8; nf++)
        #pragma unroll
        for (int t = 0; t < 4; t++) oacc[nf][t] = 0.f;

    const int arow = (w*16 + qr) * AQ;
    const int prow = (w*16 + qr) * AP;
    const int nkt  = 2*qt + 2;

    for (int kt = 0; kt < nkt; kt++) {
        __syncthreads();   // prev PV done reading V; Q visible on first iter

        // ---- load K,V tile (64x64 each), split hi/lo ----
        #pragma unroll
        for (int i = 0; i < 4; i++) {
            int idx = tid + i * 256;       // 0..1023
            int r = idx >> 4, c = (idx & 15) * 4;
            size_t g = base + (size_t)(kt*64 + r) * DIMC + c;
            float4 kv = *(const float4*)&g_k[g];
            float4 vv = *(const float4*)&g_v[g];
            float4 hi, lo;
            hi.x = tf32_rna(kv.x); lo.x = tf32_rna(kv.x - hi.x);
            hi.y = tf32_rna(kv.y); lo.y = tf32_rna(kv.y - hi.y);
            hi.z = tf32_rna(kv.z); lo.z = tf32_rna(kv.z - hi.z);
            hi.w = tf32_rna(kv.w); lo.w = tf32_rna(kv.w - hi.w);
            *(float4*)&sm[OFF_KH + r*AK + c] = hi;
            *(float4*)&sm[OFF_KL + r*AK + c] = lo;
            hi.x = tf32_rna(vv.x); lo.x = tf32_rna(vv.x - hi.x);
            hi.y = tf32_rna(vv.y); lo.y = tf32_rna(vv.y - hi.y);
            hi.z = tf32_rna(vv.z); lo.z = tf32_rna(vv.z - hi.z);
            hi.w = tf32_rna(vv.w); lo.w = tf32_rna(vv.w - hi.w);
            *(float4*)&sm[OFF_VH + r*AV + c] = hi;
            *(float4*)&sm[OFF_VL + r*AV + c] = lo;
        }
        __syncthreads();

        // ---- S = Q @ K^T  (warp: 16 rows x 64 cols), 3xTF32 ----
        float sacc[8][4];
        #pragma unroll
        for (int nf = 0; nf < 8; nf++)
            #pragma unroll
            for (int t = 0; t < 4; t++) sacc[nf][t] = 0.f;

        #pragma unroll
        for (int k8 = 0; k8 < 8; k8++) {
            const int kc = k8*8 + qc;
            uint32_t ah[4], al[4];
            ah[0] = __float_as_uint(sm[OFF_QH + arow + kc]);
            ah[1] = __float_as_uint(sm[OFF_QH + arow + 8*AQ + kc]);
            ah[2] = __float_as_uint(sm[OFF_QH + arow + kc + 4]);
            ah[3] = __float_as_uint(sm[OFF_QH + arow + 8*AQ + kc + 4]);
            al[0] = __float_as_uint(sm[OFF_QL + arow + kc]);
            al[1] = __float_as_uint(sm[OFF_QL + arow + 8*AQ + kc]);
            al[2] = __float_as_uint(sm[OFF_QL + arow + kc + 4]);
            al[3] = __float_as_uint(sm[OFF_QL + arow + 8*AQ + kc + 4]);
            #pragma unroll
            for (int nf = 0; nf < 8; nf++) {
                const int br = (nf*8 + qr) * AK;
                uint32_t bh[2], bl[2];
                bh[0] = __float_as_uint(sm[OFF_KH + br + kc]);
                bh[1] = __float_as_uint(sm[OFF_KH + br + kc + 4]);
                bl[0] = __float_as_uint(sm[OFF_KL + br + kc]);
                bl[1] = __float_as_uint(sm[OFF_KL + br + kc + 4]);
                mma_tf32(sacc[nf], ah, bh);
                mma_tf32(sacc[nf], al, bh);
                mma_tf32(sacc[nf], ah, bl);
            }
        }

        // ---- causal mask (only last two k-tiles can clip) ----
        if (kt >= 2*qt) {
            const int r0g = qt*128 + w*16 + qr;
            #pragma unroll
            for (int nf = 0; nf < 8; nf++) {
                const int cg = kt*64 + nf*8 + qc*2;
                if (cg     > r0g)     sacc[nf][0] = -1e30f;
                if (cg + 1 > r0g)     sacc[nf][1] = -1e30f;
                if (cg     > r0g + 8) sacc[nf][2] = -1e30f;
                if (cg + 1 > r0g + 8) sacc[nf][3] = -1e30f;
            }
        }

        // ---- online softmax in fragment registers (rows qr, qr+8) ----
        float mx0 = -1e30f, mx1 = -1e30f;
        #pragma unroll
        for (int nf = 0; nf < 8; nf++) {
            mx0 = fmaxf(mx0, fmaxf(sacc[nf][0], sacc[nf][1]));
            mx1 = fmaxf(mx1, fmaxf(sacc[nf][2], sacc[nf][3]));
        }
        mx0 = fmaxf(mx0, __shfl_xor_sync(0xffffffffu, mx0, 1));
        mx0 = fmaxf(mx0, __shfl_xor_sync(0xffffffffu, mx0, 2));
        mx1 = fmaxf(mx1, __shfl_xor_sync(0xffffffffu, mx1, 1));
        mx1 = fmaxf(mx1, __shfl_xor_sync(0xffffffffu, mx1, 2));

        const float nm0 = fmaxf(m0, mx0), nm1 = fmaxf(m1, mx1);
        const float c0 = fast_exp(m0 - nm0), c1 = fast_exp(m1 - nm1);
        m0 = nm0; m1 = nm1;

        float rs0 = 0.f, rs1 = 0.f;
        #pragma unroll
        for (int nf = 0; nf < 8; nf++) {
            float p0 = fast_exp(sacc[nf][0] - m0);
            float p1 = fast_exp(sacc[nf][1] - m0);
            float p2 = fast_exp(sacc[nf][2] - m1);
            float p3 = fast_exp(sacc[nf][3] - m1);
            rs0 += p0 + p1; rs1 += p2 + p3;
            float h0 = tf32_rna(p0), h1 = tf32_rna(p1);
            float h2 = tf32_rna(p2), h3 = tf32_rna(p3);
            const int col = nf*8 + qc*2;
            *(float2*)&sm[OFF_PH + prow + col]        = make_float2(h0, h1);
            *(float2*)&sm[OFF_PH + prow + 8*AP + col] = make_float2(h2, h3);
            *(float2*)&sm[OFF_PL + prow + col]        =
                make_float2(tf32_rna(p0 - h0), tf32_rna(p1 - h1));
            *(float2*)&sm[OFF_PL + prow + 8*AP + col] =
                make_float2(tf32_rna(p2 - h2), tf32_rna(p3 - h3));
        }
        rs0 += __shfl_xor_sync(0xffffffffu, rs0, 1);
        rs0 += __shfl_xor_sync(0xffffffffu, rs0, 2);
        rs1 += __shfl_xor_sync(0xffffffffu, rs1, 1);
        rs1 += __shfl_xor_sync(0xffffffffu, rs1, 2);
        l0 = l0 * c0 + rs0;
        l1 = l1 * c1 + rs1;
        #pragma unroll
        for (int nf = 0; nf < 8; nf++) {
            oacc[nf][0] *= c0; oacc[nf][1] *= c0;
            oacc[nf][2] *= c1; oacc[nf][3] *= c1;
        }

        __syncwarp();   // P rows are warp-private; warp-level visibility suffices

        // ---- O += P @ V  (3xTF32) ----
        #pragma unroll
        for (int k8 = 0; k8 < 8; k8++) {
            const int kc = k8*8 + qc;
            uint32_t ah[4], al[4];
            ah[0] = __float_as_uint(sm[OFF_PH + prow + kc]);
            ah[1] = __float_as_uint(sm[OFF_PH + prow + 8*AP + kc]);
            ah[2] = __float_as_uint(sm[OFF_PH + prow + kc + 4]);
            ah[3] = __float_as_uint(sm[OFF_PH + prow + 8*AP + kc + 4]);
            al[0] = __float_as_uint(sm[OFF_PL + prow + kc]);
            al[1] = __float_as_uint(sm[OFF_PL + prow + 8*AP + kc]);
            al[2] = __float_as_uint(sm[OFF_PL + prow + kc + 4]);
            al[3] = __float_as_uint(sm[OFF_PL + prow + 8*AP + kc + 4]);
            #pragma unroll
            for (int nf = 0; nf < 8; nf++) {
                const int bc = nf*8 + qr;
                uint32_t bh[2], bl[2];
                bh[0] = __float_as_uint(sm[OFF_VH + kc*AV + bc]);
                bh[1] = __float_as_uint(sm[OFF_VH + (kc+4)*AV + bc]);
                bl[0] = __float_as_uint(sm[OFF_VL + kc*AV + bc]);
                bl[1] = __float_as_uint(sm[OFF_VL + (kc+4)*AV + bc]);
                mma_tf32(oacc[nf], ah, bh);
                mma_tf32(oacc[nf], al, bh);
                mma_tf32(oacc[nf], ah, bl);
            }
        }
    }

    // ---- normalize + write ----
    const float inv0 = 1.f / l0, inv1 = 1.f / l1;
    const size_t r0 = (size_t)(qt*128 + w*16 + qr);
    #pragma unroll
    for (int nf = 0; nf < 8; nf++) {
        const int col = nf*8 + qc*2;
        *(float2*)&out[base + r0 * DIMC + col] =
            make_float2(oacc[nf][0]*inv0, oacc[nf][1]*inv0);
        *(float2*)&out[base + (r0+8) * DIMC + col] =
            make_float2(oacc[nf][2]*inv1, oacc[nf][3]*inv1);
    }
}

// ---------------------------------------------------------------------------
extern "C" void kernel_launch(void* const* d_in, const int* in_sizes, int n_in,
                              void* d_out, int out_size)
{
    const float* x  = (const float*)d_in[0];
    const float* Wq = (const float*)d_in[2];
    const float* Wk = (const float*)d_in[3];
    const float* Wv = (const float*)d_in[4];
    const float* Wo = (const float*)d_in[5];
    const float* bo = (const float*)d_in[6];
    float* out = (float*)d_out;

    float *q, *k, *v, *att;
    cudaGetSymbolAddress((void**)&q,   g_q);
    cudaGetSymbolAddress((void**)&k,   g_k);
    cudaGetSymbolAddress((void**)&v,   g_v);
    cudaGetSymbolAddress((void**)&att, g_att);

    cudaFuncSetAttribute(gemm_mma,
                         cudaFuncAttributeMaxDynamicSharedMemorySize, GEMM_SMEM);
    cudaFuncSetAttribute(attn_mma,
                         cudaFuncAttributeMaxDynamicSharedMemorySize, ATT_SMEM);

    dim3 gb(DIMC/128, MTOT/128);   // (8, 64)
    gemm_mma<<<gb, 256, GEMM_SMEM>>>(x,   Wq, nullptr, q);
    gemm_mma<<<gb, 256, GEMM_SMEM>>>(x,   Wk, nullptr, k);
    gemm_mma<<<gb, 256, GEMM_SMEM>>>(x,   Wv, nullptr, v);

    dim3 ga(TT/128, NH, BB);       // (16,16,4)
    attn_mma<<<ga, 256, ATT_SMEM>>>(att);

    gemm_mma<<<gb, 256, GEMM_SMEM>>>(att, Wo, bo, out);
}

// round 14
// speedup vs baseline: 1.9562x; 1.1854x over previous
#include <cuda_runtime.h>
#include <cstdint>
#include <math.h>

#define DIMC 1024
#define NH   16
#define HD   64
#define BB   4
#define TT   2048
#define MTOT (BB*TT)   /* 8192 */

// Scratch (device globals — no allocations allowed)
__device__ float g_q  [(size_t)MTOT*DIMC];
__device__ float g_k  [(size_t)MTOT*DIMC];
__device__ float g_v  [(size_t)MTOT*DIMC];
__device__ float g_att[(size_t)MTOT*DIMC];

__device__ __forceinline__ float tf32_rna(float x) {
    float y;
    asm("cvt.rna.tf32.f32 %0, %1;" : "=f"(y) : "f"(x));
    return y;
}

__device__ __forceinline__ void mma_tf32(float* d, const uint32_t* a,
                                         const uint32_t* b) {
    asm volatile(
        "mma.sync.aligned.m16n8k8.row.col.f32.tf32.tf32.f32 "
        "{%0,%1,%2,%3}, {%4,%5,%6,%7}, {%8,%9}, {%0,%1,%2,%3};"
        : "+f"(d[0]), "+f"(d[1]), "+f"(d[2]), "+f"(d[3])
        : "r"(a[0]), "r"(a[1]), "r"(a[2]), "r"(a[3]), "r"(b[0]), "r"(b[1]));
}

// Fast exp on the FMA pipe. Valid for softmax args; clamps below -87.
__device__ __forceinline__ float fast_exp(float x) {
    float z = fmaxf(x, -87.0f) * 1.4426950408889634f;   // log2(e)
    float r = z + 12582912.0f;                          // 2^23 + 2^22 magic
    int   n = __float_as_int(r) - 0x4B400000;
    float f = z - (r - 12582912.0f);
    float p = 0.0013333558f;
    p = fmaf(p, f, 0.0096181291f);
    p = fmaf(p, f, 0.0555041087f);
    p = fmaf(p, f, 0.2402265070f);
    p = fmaf(p, f, 0.6931471806f);
    p = fmaf(p, f, 1.0f);
    return p * __int_as_float((n + 127) << 23);
}

// ===========================================================================
// 3xTF32 mma.sync GEMM: C[M,N] = A[M,K] @ W[N,K]^T (+bias)  (validated R8)
// ===========================================================================
#define GEMM_SMEM (4 * 128 * 36 * 4)

__global__ __launch_bounds__(256) void gemm_mma(
    const float* __restrict__ A, const float* __restrict__ W,
    const float* __restrict__ bias, float* __restrict__ C)
{
    extern __shared__ float sm[];
    float* s_ah = sm;                 // [128][36]
    float* s_al = sm + 128*36;
    float* s_wh = sm + 2*128*36;
    float* s_wl = sm + 3*128*36;

    const int tid  = threadIdx.x;
    const int wid  = tid >> 5, lane = tid & 31;
    const int wm   = (wid & 3) * 32;
    const int wn   = (wid >> 2) * 64;
    const int bm   = blockIdx.y * 128, bn = blockIdx.x * 128;

    const int lrow = tid >> 3;
    const int lcol = (tid & 7) * 4;

    const int qr = lane >> 2;
    const int qc = lane & 3;

    float acc[2][8][4];
    #pragma unroll
    for (int i = 0; i < 2; i++)
        #pragma unroll
        for (int j = 0; j < 8; j++)
            #pragma unroll
            for (int t = 0; t < 4; t++) acc[i][j][t] = 0.f;

    float4 pa[4], pw[4];
    #pragma unroll
    for (int p = 0; p < 4; p++) {
        pa[p] = *(const float4*)&A[(size_t)(bm + lrow + 32*p) * DIMC + lcol];
        pw[p] = *(const float4*)&W[(size_t)(bn + lrow + 32*p) * DIMC + lcol];
    }

    for (int k0 = 0; k0 < DIMC; k0 += 32) {
        #pragma unroll
        for (int p = 0; p < 4; p++) {
            const int r = lrow + 32*p;
            float4 a = pa[p], w = pw[p];
            float4 ah, al, wh, wl;
            ah.x = tf32_rna(a.x); al.x = tf32_rna(a.x - ah.x);
            ah.y = tf32_rna(a.y); al.y = tf32_rna(a.y - ah.y);
            ah.z = tf32_rna(a.z); al.z = tf32_rna(a.z - ah.z);
            ah.w = tf32_rna(a.w); al.w = tf32_rna(a.w - ah.w);
            wh.x = tf32_rna(w.x); wl.x = tf32_rna(w.x - wh.x);
            wh.y = tf32_rna(w.y); wl.y = tf32_rna(w.y - wh.y);
            wh.z = tf32_rna(w.z); wl.z = tf32_rna(w.z - wh.z);
            wh.w = tf32_rna(w.w); wl.w = tf32_rna(w.w - wh.w);
            *(float4*)&s_ah[r*36 + lcol] = ah;
            *(float4*)&s_al[r*36 + lcol] = al;
            *(float4*)&s_wh[r*36 + lcol] = wh;
            *(float4*)&s_wl[r*36 + lcol] = wl;
        }
        __syncthreads();

        if (k0 + 32 < DIMC) {
            #pragma unroll
            for (int p = 0; p < 4; p++) {
                pa[p] = *(const float4*)&A[(size_t)(bm + lrow + 32*p) * DIMC + k0 + 32 + lcol];
                pw[p] = *(const float4*)&W[(size_t)(bn + lrow + 32*p) * DIMC + k0 + 32 + lcol];
            }
        }

        #pragma unroll
        for (int k8 = 0; k8 < 4; k8++) {
            const int kk = k8*8 + qc;
            uint32_t ah[2][4], al[2][4], bh[8][2], bl[8][2];
            #pragma unroll
            for (int mf = 0; mf < 2; mf++) {
                const int m = wm + mf*16 + qr;
                ah[mf][0] = __float_as_uint(s_ah[m*36 + kk]);
                ah[mf][1] = __float_as_uint(s_ah[(m+8)*36 + kk]);
                ah[mf][2] = __float_as_uint(s_ah[m*36 + kk + 4]);
                ah[mf][3] = __float_as_uint(s_ah[(m+8)*36 + kk + 4]);
                al[mf][0] = __float_as_uint(s_al[m*36 + kk]);
                al[mf][1] = __float_as_uint(s_al[(m+8)*36 + kk]);
                al[mf][2] = __float_as_uint(s_al[m*36 + kk + 4]);
                al[mf][3] = __float_as_uint(s_al[(m+8)*36 + kk + 4]);
            }
            #pragma unroll
            for (int nf = 0; nf < 8; nf++) {
                const int n = wn + nf*8 + qr;
                bh[nf][0] = __float_as_uint(s_wh[n*36 + kk]);
                bh[nf][1] = __float_as_uint(s_wh[n*36 + kk + 4]);
                bl[nf][0] = __float_as_uint(s_wl[n*36 + kk]);
                bl[nf][1] = __float_as_uint(s_wl[n*36 + kk + 4]);
            }
            #pragma unroll
            for (int mf = 0; mf < 2; mf++)
                #pragma unroll
                for (int nf = 0; nf < 8; nf++) {
                    mma_tf32(acc[mf][nf], ah[mf], bh[nf]);
                    mma_tf32(acc[mf][nf], al[mf], bh[nf]);
                    mma_tf32(acc[mf][nf], ah[mf], bl[nf]);
                }
        }
        __syncthreads();
    }

    #pragma unroll
    for (int mf = 0; mf < 2; mf++) {
        const int row = bm + wm + mf*16 + qr;
        #pragma unroll
        for (int nf = 0; nf < 8; nf++) {
            const int col = bn + wn + nf*8 + qc*2;
            float2 v0 = make_float2(acc[mf][nf][0], acc[mf][nf][1]);
            float2 v1 = make_float2(acc[mf][nf][2], acc[mf][nf][3]);
            if (bias) {
                const float b0 = bias[col], b1 = bias[col+1];
                v0.x += b0; v0.y += b1;
                v1.x += b0; v1.y += b1;
            }
            *(float2*)&C[(size_t)row     * DIMC + col] = v0;
            *(float2*)&C[(size_t)(row+8) * DIMC + col] = v1;
        }
    }
}

// ===========================================================================
// Tensor-core causal flash attention, 3xTF32 QK^T / 2-term PV.
// Block = 64 q-rows x (head, batch); 4 warps x 16 rows; 106.5KB smem
// -> 2 CTAs/SM. P never touches smem: S C-frags are permuted to PV A-frags
// with warp shfls. Strides: Q/K 68 (banks 4*qr+qc), V 72 (banks 8*qc+qr).
// ===========================================================================
#define AQ 68
#define AK 68
#define AV 72
#define OFF_QH 0
#define OFF_QL (64*AQ)
#define OFF_KH (2*64*AQ)
#define OFF_KL (OFF_KH + 64*AK)
#define OFF_VH (OFF_KL + 64*AK)
#define OFF_VL (OFF_VH + 64*AV)
#define ATT_SMEM ((OFF_VL + 64*AV) * 4)   /* 106496 B -> 2 CTAs/SM */

__global__ __launch_bounds__(128) void attn_mma(float* __restrict__ out)
{
    extern __shared__ float sm[];
    const int tid  = threadIdx.x;
    const int w    = tid >> 5, lane = tid & 31;
    const int qr   = lane >> 2, qc = lane & 3;
    const int qt   = blockIdx.x, h = blockIdx.y, b = blockIdx.z;
    const size_t base = ((size_t)b * TT) * DIMC + (size_t)h * HD;

    // ---- load Q tile (64x64), fold scale 1/8 (exact pow2), split hi/lo ----
    #pragma unroll
    for (int i = 0; i < 8; i++) {
        int idx = tid + i * 128;           // 0..1023
        int r = idx >> 4, c = (idx & 15) * 4;
        float4 v = *(const float4*)&g_q[base + (size_t)(qt*64 + r) * DIMC + c];
        v.x *= 0.125f; v.y *= 0.125f; v.z *= 0.125f; v.w *= 0.125f;
        float4 hi, lo;
        hi.x = tf32_rna(v.x); lo.x = tf32_rna(v.x - hi.x);
        hi.y = tf32_rna(v.y); lo.y = tf32_rna(v.y - hi.y);
        hi.z = tf32_rna(v.z); lo.z = tf32_rna(v.z - hi.z);
        hi.w = tf32_rna(v.w); lo.w = tf32_rna(v.w - hi.w);
        *(float4*)&sm[OFF_QH + r*AQ + c] = hi;
        *(float4*)&sm[OFF_QL + r*AQ + c] = lo;
    }

    float m0 = -1e30f, m1 = -1e30f, l0 = 0.f, l1 = 0.f;
    float oacc[8][4];
    #pragma unroll
    for (int nf = 0; nf < 8; nf++)
        #pragma unroll
        for (int t = 0; t < 4; t++) oacc[nf][t] = 0.f;

    const int arow = (w*16 + qr) * AQ;
    const int nkt  = qt + 1;
    const int srcA = 4*qr + (qc >> 1);     // owner of col qc within 8-col group
    const int srcB = srcA + 2;             // owner of col qc+4
    const bool oddc = (qc & 1);

    for (int kt = 0; kt < nkt; kt++) {
        __syncthreads();   // prev PV done reading V; Q visible on first iter

        // ---- load K,V tile (64x64 each), split hi/lo ----
        #pragma unroll
        for (int i = 0; i < 8; i++) {
            int idx = tid + i * 128;       // 0..1023
            int r = idx >> 4, c = (idx & 15) * 4;
            size_t g = base + (size_t)(kt*64 + r) * DIMC + c;
            float4 kv = *(const float4*)&g_k[g];
            float4 vv = *(const float4*)&g_v[g];
            float4 hi, lo;
            hi.x = tf32_rna(kv.x); lo.x = tf32_rna(kv.x - hi.x);
            hi.y = tf32_rna(kv.y); lo.y = tf32_rna(kv.y - hi.y);
            hi.z = tf32_rna(kv.z); lo.z = tf32_rna(kv.z - hi.z);
            hi.w = tf32_rna(kv.w); lo.w = tf32_rna(kv.w - hi.w);
            *(float4*)&sm[OFF_KH + r*AK + c] = hi;
            *(float4*)&sm[OFF_KL + r*AK + c] = lo;
            hi.x = tf32_rna(vv.x); lo.x = tf32_rna(vv.x - hi.x);
            hi.y = tf32_rna(vv.y); lo.y = tf32_rna(vv.y - hi.y);
            hi.z = tf32_rna(vv.z); lo.z = tf32_rna(vv.z - hi.z);
            hi.w = tf32_rna(vv.w); lo.w = tf32_rna(vv.w - hi.w);
            *(float4*)&sm[OFF_VH + r*AV + c] = hi;
            *(float4*)&sm[OFF_VL + r*AV + c] = lo;
        }
        __syncthreads();

        // ---- S = Q @ K^T  (warp: 16 rows x 64 cols), 3xTF32 ----
        float sacc[8][4];
        #pragma unroll
        for (int nf = 0; nf < 8; nf++)
            #pragma unroll
            for (int t = 0; t < 4; t++) sacc[nf][t] = 0.f;

        #pragma unroll
        for (int k8 = 0; k8 < 8; k8++) {
            const int kc = k8*8 + qc;
            uint32_t ah[4], al[4];
            ah[0] = __float_as_uint(sm[OFF_QH + arow + kc]);
            ah[1] = __float_as_uint(sm[OFF_QH + arow + 8*AQ + kc]);
            ah[2] = __float_as_uint(sm[OFF_QH + arow + kc + 4]);
            ah[3] = __float_as_uint(sm[OFF_QH + arow + 8*AQ + kc + 4]);
            al[0] = __float_as_uint(sm[OFF_QL + arow + kc]);
            al[1] = __float_as_uint(sm[OFF_QL + arow + 8*AQ + kc]);
            al[2] = __float_as_uint(sm[OFF_QL + arow + kc + 4]);
            al[3] = __float_as_uint(sm[OFF_QL + arow + 8*AQ + kc + 4]);
            #pragma unroll
            for (int nf = 0; nf < 8; nf++) {
                const int br = (nf*8 + qr) * AK;
                uint32_t bh[2], bl[2];
                bh[0] = __float_as_uint(sm[OFF_KH + br + kc]);
                bh[1] = __float_as_uint(sm[OFF_KH + br + kc + 4]);
                bl[0] = __float_as_uint(sm[OFF_KL + br + kc]);
                bl[1] = __float_as_uint(sm[OFF_KL + br + kc + 4]);
                mma_tf32(sacc[nf], ah, bh);
                mma_tf32(sacc[nf], al, bh);
                mma_tf32(sacc[nf], ah, bl);
            }
        }

        // ---- causal mask (only diagonal tile clips) ----
        if (kt == qt) {
            const int r0g = qt*64 + w*16 + qr;
            #pragma unroll
            for (int nf = 0; nf < 8; nf++) {
                const int cg = kt*64 + nf*8 + qc*2;
                if (cg     > r0g)     sacc[nf][0] = -1e30f;
                if (cg + 1 > r0g)     sacc[nf][1] = -1e30f;
                if (cg     > r0g + 8) sacc[nf][2] = -1e30f;
                if (cg + 1 > r0g + 8) sacc[nf][3] = -1e30f;
            }
        }

        // ---- online softmax in registers (rows qr, qr+8) ----
        float mx0 = -1e30f, mx1 = -1e30f;
        #pragma unroll
        for (int nf = 0; nf < 8; nf++) {
            mx0 = fmaxf(mx0, fmaxf(sacc[nf][0], sacc[nf][1]));
            mx1 = fmaxf(mx1, fmaxf(sacc[nf][2], sacc[nf][3]));
        }
        mx0 = fmaxf(mx0, __shfl_xor_sync(0xffffffffu, mx0, 1));
        mx0 = fmaxf(mx0, __shfl_xor_sync(0xffffffffu, mx0, 2));
        mx1 = fmaxf(mx1, __shfl_xor_sync(0xffffffffu, mx1, 1));
        mx1 = fmaxf(mx1, __shfl_xor_sync(0xffffffffu, mx1, 2));

        const float nm0 = fmaxf(m0, mx0), nm1 = fmaxf(m1, mx1);
        const float c0 = fast_exp(m0 - nm0), c1 = fast_exp(m1 - nm1);
        m0 = nm0; m1 = nm1;

        float rs0 = 0.f, rs1 = 0.f;
        #pragma unroll
        for (int nf = 0; nf < 8; nf++) {
            float p0 = tf32_rna(fast_exp(sacc[nf][0] - m0));
            float p1 = tf32_rna(fast_exp(sacc[nf][1] - m0));
            float p2 = tf32_rna(fast_exp(sacc[nf][2] - m1));
            float p3 = tf32_rna(fast_exp(sacc[nf][3] - m1));
            rs0 += p0 + p1; rs1 += p2 + p3;
            sacc[nf][0] = p0; sacc[nf][1] = p1;
            sacc[nf][2] = p2; sacc[nf][3] = p3;
        }
        rs0 += __shfl_xor_sync(0xffffffffu, rs0, 1);
        rs0 += __shfl_xor_sync(0xffffffffu, rs0, 2);
        rs1 += __shfl_xor_sync(0xffffffffu, rs1, 1);
        rs1 += __shfl_xor_sync(0xffffffffu, rs1, 2);
        l0 = l0 * c0 + rs0;
        l1 = l1 * c1 + rs1;
        #pragma unroll
        for (int nf = 0; nf < 8; nf++) {
            oacc[nf][0] *= c0; oacc[nf][1] *= c0;
            oacc[nf][2] *= c1; oacc[nf][3] *= c1;
        }

        // ---- O += P @ V : permute P C-frags -> A-frags via shfl, 2-term ----
        #pragma unroll
        for (int k8 = 0; k8 < 8; k8++) {
            float v0 = __shfl_sync(0xffffffffu, sacc[k8][0], srcA);
            float v1 = __shfl_sync(0xffffffffu, sacc[k8][1], srcA);
            float v2 = __shfl_sync(0xffffffffu, sacc[k8][2], srcA);
            float v3 = __shfl_sync(0xffffffffu, sacc[k8][3], srcA);
            float w0 = __shfl_sync(0xffffffffu, sacc[k8][0], srcB);
            float w1 = __shfl_sync(0xffffffffu, sacc[k8][1], srcB);
            float w2 = __shfl_sync(0xffffffffu, sacc[k8][2], srcB);
            float w3 = __shfl_sync(0xffffffffu, sacc[k8][3], srcB);
            uint32_t ap[4];
            ap[0] = __float_as_uint(oddc ? v1 : v0);
            ap[1] = __float_as_uint(oddc ? v3 : v2);
            ap[2] = __float_as_uint(oddc ? w1 : w0);
            ap[3] = __float_as_uint(oddc ? w3 : w2);
            const int kc = k8*8 + qc;
            #pragma unroll
            for (int nf = 0; nf < 8; nf++) {
                const int bc = nf*8 + qr;
                uint32_t bh[2], bl[2];
                bh[0] = __float_as_uint(sm[OFF_VH + kc*AV + bc]);
                bh[1] = __float_as_uint(sm[OFF_VH + (kc+4)*AV + bc]);
                bl[0] = __float_as_uint(sm[OFF_VL + kc*AV + bc]);
                bl[1] = __float_as_uint(sm[OFF_VL + (kc+4)*AV + bc]);
                mma_tf32(oacc[nf], ap, bh);
                mma_tf32(oacc[nf], ap, bl);
            }
        }
    }

    // ---- normalize + write ----
    const float inv0 = 1.f / l0, inv1 = 1.f / l1;
    const size_t r0 = (size_t)(qt*64 + w*16 + qr);
    #pragma unroll
    for (int nf = 0; nf < 8; nf++) {
        const int col = nf*8 + qc*2;
        *(float2*)&out[base + r0 * DIMC + col] =
            make_float2(oacc[nf][0]*inv0, oacc[nf][1]*inv0);
        *(float2*)&out[base + (r0+8) * DIMC + col] =
            make_float2(oacc[nf][2]*inv1, oacc[nf][3]*inv1);
    }
}

// ---------------------------------------------------------------------------
extern "C" void kernel_launch(void* const* d_in, const int* in_sizes, int n_in,
                              void* d_out, int out_size)
{
    const float* x  = (const float*)d_in[0];
    const float* Wq = (const float*)d_in[2];
    const float* Wk = (const float*)d_in[3];
    const float* Wv = (const float*)d_in[4];
    const float* Wo = (const float*)d_in[5];
    const float* bo = (const float*)d_in[6];
    float* out = (float*)d_out;

    float *q, *k, *v, *att;
    cudaGetSymbolAddress((void**)&q,   g_q);
    cudaGetSymbolAddress((void**)&k,   g_k);
    cudaGetSymbolAddress((void**)&v,   g_v);
    cudaGetSymbolAddress((void**)&att, g_att);

    cudaFuncSetAttribute(gemm_mma,
                         cudaFuncAttributeMaxDynamicSharedMemorySize, GEMM_SMEM);
    cudaFuncSetAttribute(attn_mma,
                         cudaFuncAttributeMaxDynamicSharedMemorySize, ATT_SMEM);

    dim3 gb(DIMC/128, MTOT/128);   // (8, 64)
    gemm_mma<<<gb, 256, GEMM_SMEM>>>(x,   Wq, nullptr, q);
    gemm_mma<<<gb, 256, GEMM_SMEM>>>(x,   Wk, nullptr, k);
    gemm_mma<<<gb, 256, GEMM_SMEM>>>(x,   Wv, nullptr, v);

    dim3 ga(TT/64, NH, BB);        // (32,16,4)
    attn_mma<<<ga, 128, ATT_SMEM>>>(att);

    gemm_mma<<<gb, 256, GEMM_SMEM>>>(att, Wo, bo, out);
}

// round 15
// speedup vs baseline: 2.5110x; 1.2836x over previous
#include <cuda_runtime.h>
#include <cstdint>
#include <math.h>

#define DIMC 1024
#define NH   16
#define HD   64
#define BB   4
#define TT   2048
#define MTOT (BB*TT)   /* 8192 */

// Scratch (device globals — no allocations allowed)
__device__ float g_q  [(size_t)MTOT*DIMC];
__device__ float g_k  [(size_t)MTOT*DIMC];
__device__ float g_v  [(size_t)MTOT*DIMC];
__device__ float g_att[(size_t)MTOT*DIMC];

// ---- bf16 split helpers (ALU-pipe rounding, no MUFU/cvt funnel) ----------
__device__ __forceinline__ uint32_t bf16_rn_bits(float x) {
    uint32_t u = __float_as_uint(x);
    return (u + 0x7FFFu + ((u >> 16) & 1u)) & 0xFFFF0000u;
}
__device__ __forceinline__ float bf16_rn_f(float x) {
    return __uint_as_float(bf16_rn_bits(x));
}
// word = {low half: lo_elem(k), high half: hi_elem(k+1)}
__device__ __forceinline__ uint32_t pack_bf16(float lo_elem, float hi_elem) {
    return bf16_rn_bits(hi_elem) | (bf16_rn_bits(lo_elem) >> 16);
}

__device__ __forceinline__ void mma_bf16(float* d, const uint32_t* a,
                                         const uint32_t* b) {
    asm volatile(
        "mma.sync.aligned.m16n8k16.row.col.f32.bf16.bf16.f32 "
        "{%0,%1,%2,%3}, {%4,%5,%6,%7}, {%8,%9}, {%0,%1,%2,%3};"
        : "+f"(d[0]), "+f"(d[1]), "+f"(d[2]), "+f"(d[3])
        : "r"(a[0]), "r"(a[1]), "r"(a[2]), "r"(a[3]), "r"(b[0]), "r"(b[1]));
}

// Fast exp on the FMA pipe. Valid for softmax args; clamps below -87.
__device__ __forceinline__ float fast_exp(float x) {
    float z = fmaxf(x, -87.0f) * 1.4426950408889634f;   // log2(e)
    float r = z + 12582912.0f;                          // 2^23 + 2^22 magic
    int   n = __float_as_int(r) - 0x4B400000;
    float f = z - (r - 12582912.0f);
    float p = 0.0013333558f;
    p = fmaf(p, f, 0.0096181291f);
    p = fmaf(p, f, 0.0555041087f);
    p = fmaf(p, f, 0.2402265070f);
    p = fmaf(p, f, 0.6931471806f);
    p = fmaf(p, f, 1.0f);
    return p * __int_as_float((n + 127) << 23);
}

// ===========================================================================
// Split-BF16 (3-term) mma.sync GEMM: C[M,N] = A[M,K] @ W[N,K]^T (+bias)
// CTA tile 128x128, 8 warps (4M x 2N), warp tile 32x64, BK=32.
// smem: packed bf16x2 words, 16 words/row used, stride 20 (conflict-free frags)
// 4 arrays * 128*20 words * 4B = 40960 B.
// ===========================================================================
#define GEMM_SMEM (4 * 128 * 20 * 4)

__global__ __launch_bounds__(256) void gemm_bf16(
    const float* __restrict__ A, const float* __restrict__ W,
    const float* __restrict__ bias, float* __restrict__ C)
{
    extern __shared__ uint32_t gsw[];
    uint32_t* s_ah = gsw;                  // [128][20]
    uint32_t* s_al = gsw + 128*20;
    uint32_t* s_wh = gsw + 2*128*20;
    uint32_t* s_wl = gsw + 3*128*20;

    const int tid  = threadIdx.x;
    const int wid  = tid >> 5, lane = tid & 31;
    const int wm   = (wid & 3) * 32;
    const int wn   = (wid >> 2) * 64;
    const int bm   = blockIdx.y * 128, bn = blockIdx.x * 128;

    const int lrow = tid >> 3;             // 0..31
    const int lcol = (tid & 7) * 4;        // k offset 0..28
    const int wt2  = (tid & 7) * 2;        // word offset 0..14

    const int qr = lane >> 2;
    const int qc = lane & 3;

    float acc[2][8][4];
    #pragma unroll
    for (int i = 0; i < 2; i++)
        #pragma unroll
        for (int j = 0; j < 8; j++)
            #pragma unroll
            for (int t = 0; t < 4; t++) acc[i][j][t] = 0.f;

    float4 pa[4], pw[4];
    #pragma unroll
    for (int p = 0; p < 4; p++) {
        pa[p] = *(const float4*)&A[(size_t)(bm + lrow + 32*p) * DIMC + lcol];
        pw[p] = *(const float4*)&W[(size_t)(bn + lrow + 32*p) * DIMC + lcol];
    }

    for (int k0 = 0; k0 < DIMC; k0 += 32) {
        #pragma unroll
        for (int p = 0; p < 4; p++) {
            const int r = lrow + 32*p;
            float4 a = pa[p], w = pw[p];
            // A split + pack
            uint32_t hx = bf16_rn_bits(a.x), hy = bf16_rn_bits(a.y);
            uint32_t hz = bf16_rn_bits(a.z), hw_ = bf16_rn_bits(a.w);
            float lx = a.x - __uint_as_float(hx), ly = a.y - __uint_as_float(hy);
            float lz = a.z - __uint_as_float(hz), lw = a.w - __uint_as_float(hw_);
            *(uint2*)&s_ah[r*20 + wt2] =
                make_uint2(hy | (hx >> 16), hw_ | (hz >> 16));
            *(uint2*)&s_al[r*20 + wt2] =
                make_uint2(pack_bf16(lx, ly), pack_bf16(lz, lw));
            // W split + pack
            hx = bf16_rn_bits(w.x); hy = bf16_rn_bits(w.y);
            hz = bf16_rn_bits(w.z); hw_ = bf16_rn_bits(w.w);
            lx = w.x - __uint_as_float(hx); ly = w.y - __uint_as_float(hy);
            lz = w.z - __uint_as_float(hz); lw = w.w - __uint_as_float(hw_);
            *(uint2*)&s_wh[r*20 + wt2] =
                make_uint2(hy | (hx >> 16), hw_ | (hz >> 16));
            *(uint2*)&s_wl[r*20 + wt2] =
                make_uint2(pack_bf16(lx, ly), pack_bf16(lz, lw));
        }
        __syncthreads();

        if (k0 + 32 < DIMC) {
            #pragma unroll
            for (int p = 0; p < 4; p++) {
                pa[p] = *(const float4*)&A[(size_t)(bm + lrow + 32*p) * DIMC + k0 + 32 + lcol];
                pw[p] = *(const float4*)&W[(size_t)(bn + lrow + 32*p) * DIMC + k0 + 32 + lcol];
            }
        }

        #pragma unroll
        for (int k16 = 0; k16 < 2; k16++) {
            const int kw = k16*8 + qc;
            uint32_t ah[2][4], al[2][4], bh[8][2], bl[8][2];
            #pragma unroll
            for (int mf = 0; mf < 2; mf++) {
                const int m = (wm + mf*16 + qr) * 20;
                ah[mf][0] = s_ah[m + kw];
                ah[mf][1] = s_ah[m + 8*20 + kw];
                ah[mf][2] = s_ah[m + kw + 4];
                ah[mf][3] = s_ah[m + 8*20 + kw + 4];
                al[mf][0] = s_al[m + kw];
                al[mf][1] = s_al[m + 8*20 + kw];
                al[mf][2] = s_al[m + kw + 4];
                al[mf][3] = s_al[m + 8*20 + kw + 4];
            }
            #pragma unroll
            for (int nf = 0; nf < 8; nf++) {
                const int n = (wn + nf*8 + qr) * 20;
                bh[nf][0] = s_wh[n + kw];
                bh[nf][1] = s_wh[n + kw + 4];
                bl[nf][0] = s_wl[n + kw];
                bl[nf][1] = s_wl[n + kw + 4];
            }
            #pragma unroll
            for (int mf = 0; mf < 2; mf++)
                #pragma unroll
                for (int nf = 0; nf < 8; nf++) {
                    mma_bf16(acc[mf][nf], ah[mf], bh[nf]);
                    mma_bf16(acc[mf][nf], al[mf], bh[nf]);
                    mma_bf16(acc[mf][nf], ah[mf], bl[nf]);
                }
        }
        __syncthreads();
    }

    #pragma unroll
    for (int mf = 0; mf < 2; mf++) {
        const int row = bm + wm + mf*16 + qr;
        #pragma unroll
        for (int nf = 0; nf < 8; nf++) {
            const int col = bn + wn + nf*8 + qc*2;
            float2 v0 = make_float2(acc[mf][nf][0], acc[mf][nf][1]);
            float2 v1 = make_float2(acc[mf][nf][2], acc[mf][nf][3]);
            if (bias) {
                const float b0 = bias[col], b1 = bias[col+1];
                v0.x += b0; v0.y += b1;
                v1.x += b0; v1.y += b1;
            }
            *(float2*)&C[(size_t)row     * DIMC + col] = v0;
            *(float2*)&C[(size_t)(row+8) * DIMC + col] = v1;
        }
    }
}

// ===========================================================================
// Split-BF16 causal flash attention.
// Block = 64 q-rows x (head, batch); 4 warps x 16 rows.
// Packed bf16x2 words, row stride 36 words. Q/K natural K-packing; V stored
// transposed K-packed (built with STS.128). P never leaves registers: its
// C-fragments pack directly into k16 A-fragments (same-lane property).
// smem: 6 arrays * 64*36 words * 4B = 55296 B -> 2 CTAs/SM.
// ===========================================================================
#define SQW 36
#define WQH 0
#define WQL (64*SQW)
#define WKH (2*64*SQW)
#define WKL (3*64*SQW)
#define WVH (4*64*SQW)
#define WVL (5*64*SQW)
#define ATT_SMEM (6 * 64 * SQW * 4)   /* 55296 B */

__global__ __launch_bounds__(128) void attn_bf16(float* __restrict__ out)
{
    extern __shared__ uint32_t smw[];
    const int tid  = threadIdx.x;
    const int w    = tid >> 5, lane = tid & 31;
    const int qr   = lane >> 2, qc = lane & 3;
    const int qt   = blockIdx.x, h = blockIdx.y, b = blockIdx.z;
    const size_t base = ((size_t)b * TT) * DIMC + (size_t)h * HD;

    // ---- load Q tile (64x64), fold 1/8 scale, split+pack ----
    #pragma unroll
    for (int i = 0; i < 8; i++) {
        int idx = tid + i * 128;           // 0..1023
        int r = idx >> 4, c4 = idx & 15;
        float4 v = *(const float4*)&g_q[base + (size_t)(qt*64 + r) * DIMC + c4*4];
        v.x *= 0.125f; v.y *= 0.125f; v.z *= 0.125f; v.w *= 0.125f;
        uint32_t hx = bf16_rn_bits(v.x), hy = bf16_rn_bits(v.y);
        uint32_t hz = bf16_rn_bits(v.z), hw_ = bf16_rn_bits(v.w);
        float lx = v.x - __uint_as_float(hx), ly = v.y - __uint_as_float(hy);
        float lz = v.z - __uint_as_float(hz), lw = v.w - __uint_as_float(hw_);
        *(uint2*)&smw[WQH + r*SQW + c4*2] =
            make_uint2(hy | (hx >> 16), hw_ | (hz >> 16));
        *(uint2*)&smw[WQL + r*SQW + c4*2] =
            make_uint2(pack_bf16(lx, ly), pack_bf16(lz, lw));
    }

    float m0 = -1e30f, m1 = -1e30f, l0 = 0.f, l1 = 0.f;
    float oacc[8][4];
    #pragma unroll
    for (int nf = 0; nf < 8; nf++)
        #pragma unroll
        for (int t = 0; t < 4; t++) oacc[nf][t] = 0.f;

    const int arow = (w*16 + qr) * SQW;
    const int nkt  = qt + 1;
    const int vn   = tid & 63;             // V-transpose loader column
    const int vrb0 = tid >> 6;             // 0..1

    for (int kt = 0; kt < nkt; kt++) {
        __syncthreads();   // prev iter done reading smem

        // ---- K tile (64x64): natural K-packed split ----
        #pragma unroll
        for (int i = 0; i < 8; i++) {
            int idx = tid + i * 128;
            int r = idx >> 4, c4 = idx & 15;
            float4 v = *(const float4*)&g_k[base + (size_t)(kt*64 + r) * DIMC + c4*4];
            uint32_t hx = bf16_rn_bits(v.x), hy = bf16_rn_bits(v.y);
            uint32_t hz = bf16_rn_bits(v.z), hw_ = bf16_rn_bits(v.w);
            float lx = v.x - __uint_as_float(hx), ly = v.y - __uint_as_float(hy);
            float lz = v.z - __uint_as_float(hz), lw = v.w - __uint_as_float(hw_);
            *(uint2*)&smw[WKH + r*SQW + c4*2] =
                make_uint2(hy | (hx >> 16), hw_ | (hz >> 16));
            *(uint2*)&smw[WKL + r*SQW + c4*2] =
                make_uint2(pack_bf16(lx, ly), pack_bf16(lz, lw));
        }

        // ---- V tile: transposed K-packed (vword[n][token/2]) ----
        #pragma unroll
        for (int i = 0; i < 4; i++) {
            const int rb = vrb0 + 2*i;     // 0..7: tokens 8rb..8rb+7
            float v0[8];
            #pragma unroll
            for (int s = 0; s < 8; s++)
                v0[s] = g_v[base + (size_t)(kt*64 + rb*8 + s) * DIMC + vn];
            uint32_t hb[8]; float lo[8];
            #pragma unroll
            for (int s = 0; s < 8; s++) {
                hb[s] = bf16_rn_bits(v0[s]);
                lo[s] = v0[s] - __uint_as_float(hb[s]);
            }
            *(uint4*)&smw[WVH + vn*SQW + rb*4] = make_uint4(
                hb[1] | (hb[0] >> 16), hb[3] | (hb[2] >> 16),
                hb[5] | (hb[4] >> 16), hb[7] | (hb[6] >> 16));
            *(uint4*)&smw[WVL + vn*SQW + rb*4] = make_uint4(
                pack_bf16(lo[0], lo[1]), pack_bf16(lo[2], lo[3]),
                pack_bf16(lo[4], lo[5]), pack_bf16(lo[6], lo[7]));
        }
        __syncthreads();

        // ---- S = Q @ K^T (warp: 16 rows x 64 cols), 3-term bf16 ----
        float sacc[8][4];
        #pragma unroll
        for (int nf = 0; nf < 8; nf++)
            #pragma unroll
            for (int t = 0; t < 4; t++) sacc[nf][t] = 0.f;

        #pragma unroll
        for (int k16 = 0; k16 < 4; k16++) {
            const int kw = k16*8 + qc;
            uint32_t ah[4], al[4];
            ah[0] = smw[WQH + arow + kw];
            ah[1] = smw[WQH + arow + 8*SQW + kw];
            ah[2] = smw[WQH + arow + kw + 4];
            ah[3] = smw[WQH + arow + 8*SQW + kw + 4];
            al[0] = smw[WQL + arow + kw];
            al[1] = smw[WQL + arow + 8*SQW + kw];
            al[2] = smw[WQL + arow + kw + 4];
            al[3] = smw[WQL + arow + 8*SQW + kw + 4];
            #pragma unroll
            for (int nf = 0; nf < 8; nf++) {
                const int br = (nf*8 + qr) * SQW;
                uint32_t bh[2], bl[2];
                bh[0] = smw[WKH + br + kw];
                bh[1] = smw[WKH + br + kw + 4];
                bl[0] = smw[WKL + br + kw];
                bl[1] = smw[WKL + br + kw + 4];
                mma_bf16(sacc[nf], ah, bh);
                mma_bf16(sacc[nf], al, bh);
                mma_bf16(sacc[nf], ah, bl);
            }
        }

        // ---- causal mask (diagonal tile only) ----
        if (kt == qt) {
            const int r0g = qt*64 + w*16 + qr;
            #pragma unroll
            for (int nf = 0; nf < 8; nf++) {
                const int cg = kt*64 + nf*8 + qc*2;
                if (cg     > r0g)     sacc[nf][0] = -1e30f;
                if (cg + 1 > r0g)     sacc[nf][1] = -1e30f;
                if (cg     > r0g + 8) sacc[nf][2] = -1e30f;
                if (cg + 1 > r0g + 8) sacc[nf][3] = -1e30f;
            }
        }

        // ---- online softmax in registers (rows qr, qr+8) ----
        float mx0 = -1e30f, mx1 = -1e30f;
        #pragma unroll
        for (int nf = 0; nf < 8; nf++) {
            mx0 = fmaxf(mx0, fmaxf(sacc[nf][0], sacc[nf][1]));
            mx1 = fmaxf(mx1, fmaxf(sacc[nf][2], sacc[nf][3]));
        }
        mx0 = fmaxf(mx0, __shfl_xor_sync(0xffffffffu, mx0, 1));
        mx0 = fmaxf(mx0, __shfl_xor_sync(0xffffffffu, mx0, 2));
        mx1 = fmaxf(mx1, __shfl_xor_sync(0xffffffffu, mx1, 1));
        mx1 = fmaxf(mx1, __shfl_xor_sync(0xffffffffu, mx1, 2));

        const float nm0 = fmaxf(m0, mx0), nm1 = fmaxf(m1, mx1);
        const float c0 = fast_exp(m0 - nm0), c1 = fast_exp(m1 - nm1);
        m0 = nm0; m1 = nm1;

        float rs0 = 0.f, rs1 = 0.f;
        #pragma unroll
        for (int nf = 0; nf < 8; nf++) {
            float p0 = fast_exp(sacc[nf][0] - m0);
            float p1 = fast_exp(sacc[nf][1] - m0);
            float p2 = fast_exp(sacc[nf][2] - m1);
            float p3 = fast_exp(sacc[nf][3] - m1);
            rs0 += p0 + p1; rs1 += p2 + p3;
            sacc[nf][0] = p0; sacc[nf][1] = p1;
            sacc[nf][2] = p2; sacc[nf][3] = p3;
        }
        rs0 += __shfl_xor_sync(0xffffffffu, rs0, 1);
        rs0 += __shfl_xor_sync(0xffffffffu, rs0, 2);
        rs1 += __shfl_xor_sync(0xffffffffu, rs1, 1);
        rs1 += __shfl_xor_sync(0xffffffffu, rs1, 2);
        l0 = l0 * c0 + rs0;
        l1 = l1 * c1 + rs1;
        #pragma unroll
        for (int nf = 0; nf < 8; nf++) {
            oacc[nf][0] *= c0; oacc[nf][1] *= c0;
            oacc[nf][2] *= c1; oacc[nf][3] *= c1;
        }

        // ---- O += P @ V : same-lane C-frag -> A-frag packing, 3-term ----
        #pragma unroll
        for (int k16 = 0; k16 < 4; k16++) {
            const int g0 = 2*k16, g1 = 2*k16 + 1;
            uint32_t aph[4], apl[4];
            {
                uint32_t h00 = bf16_rn_bits(sacc[g0][0]);
                uint32_t h01 = bf16_rn_bits(sacc[g0][1]);
                uint32_t h02 = bf16_rn_bits(sacc[g0][2]);
                uint32_t h03 = bf16_rn_bits(sacc[g0][3]);
                uint32_t h10 = bf16_rn_bits(sacc[g1][0]);
                uint32_t h11 = bf16_rn_bits(sacc[g1][1]);
                uint32_t h12 = bf16_rn_bits(sacc[g1][2]);
                uint32_t h13 = bf16_rn_bits(sacc[g1][3]);
                aph[0] = h01 | (h00 >> 16);
                aph[1] = h03 | (h02 >> 16);
                aph[2] = h11 | (h10 >> 16);
                aph[3] = h13 | (h12 >> 16);
                apl[0] = pack_bf16(sacc[g0][0] - __uint_as_float(h00),
                                   sacc[g0][1] - __uint_as_float(h01));
                apl[1] = pack_bf16(sacc[g0][2] - __uint_as_float(h02),
                                   sacc[g0][3] - __uint_as_float(h03));
                apl[2] = pack_bf16(sacc[g1][0] - __uint_as_float(h10),
                                   sacc[g1][1] - __uint_as_float(h11));
                apl[3] = pack_bf16(sacc[g1][2] - __uint_as_float(h12),
                                   sacc[g1][3] - __uint_as_float(h13));
            }
            const int kw = k16*8 + qc;
            #pragma unroll
            for (int nf = 0; nf < 8; nf++) {
                const int bn_ = (nf*8 + qr) * SQW;
                uint32_t bh[2], bl[2];
                bh[0] = smw[WVH + bn_ + kw];
                bh[1] = smw[WVH + bn_ + kw + 4];
                bl[0] = smw[WVL + bn_ + kw];
                bl[1] = smw[WVL + bn_ + kw + 4];
                mma_bf16(oacc[nf], aph, bh);
                mma_bf16(oacc[nf], apl, bh);
                mma_bf16(oacc[nf], aph, bl);
            }
        }
    }

    // ---- normalize + write ----
    const float inv0 = 1.f / l0, inv1 = 1.f / l1;
    const size_t r0 = (size_t)(qt*64 + w*16 + qr);
    #pragma unroll
    for (int nf = 0; nf < 8; nf++) {
        const int col = nf*8 + qc*2;
        *(float2*)&out[base + r0 * DIMC + col] =
            make_float2(oacc[nf][0]*inv0, oacc[nf][1]*inv0);
        *(float2*)&out[base + (r0+8) * DIMC + col] =
            make_float2(oacc[nf][2]*inv1, oacc[nf][3]*inv1);
    }
}

// ---------------------------------------------------------------------------
extern "C" void kernel_launch(void* const* d_in, const int* in_sizes, int n_in,
                              void* d_out, int out_size)
{
    const float* x  = (const float*)d_in[0];
    const float* Wq = (const float*)d_in[2];
    const float* Wk = (const float*)d_in[3];
    const float* Wv = (const float*)d_in[4];
    const float* Wo = (const float*)d_in[5];
    const float* bo = (const float*)d_in[6];
    float* out = (float*)d_out;

    float *q, *k, *v, *att;
    cudaGetSymbolAddress((void**)&q,   g_q);
    cudaGetSymbolAddress((void**)&k,   g_k);
    cudaGetSymbolAddress((void**)&v,   g_v);
    cudaGetSymbolAddress((void**)&att, g_att);

    cudaFuncSetAttribute(gemm_bf16,
                         cudaFuncAttributeMaxDynamicSharedMemorySize, GEMM_SMEM);
    cudaFuncSetAttribute(attn_bf16,
                         cudaFuncAttributeMaxDynamicSharedMemorySize, ATT_SMEM);

    dim3 gb(DIMC/128, MTOT/128);   // (8, 64)
    gemm_bf16<<<gb, 256, GEMM_SMEM>>>(x,   Wq, nullptr, q);
    gemm_bf16<<<gb, 256, GEMM_SMEM>>>(x,   Wk, nullptr, k);
    gemm_bf16<<<gb, 256, GEMM_SMEM>>>(x,   Wv, nullptr, v);

    dim3 ga(TT/64, NH, BB);        // (32,16,4)
    attn_bf16<<<ga, 128, ATT_SMEM>>>(att);

    gemm_bf16<<<gb, 256, GEMM_SMEM>>>(att, Wo, bo, out);
}

// round 16
// speedup vs baseline: 2.7499x; 1.0951x over previous
#include <cuda_runtime.h>
#include <cstdint>
#include <math.h>

#define DIMC 1024
#define NH   16
#define HD   64
#define BB   4
#define TT   2048
#define MTOT (BB*TT)   /* 8192 */
#define MW   ((size_t)MTOT*512)    /* packed words per activation buffer */
#define WW   ((size_t)1024*512)    /* packed words per weight buffer */

// Packed bf16 hi/lo buffers (device globals — no allocations allowed)
__device__ uint32_t g_xh[MW],  g_xl[MW];
__device__ uint32_t g_qh[MW],  g_ql[MW];
__device__ uint32_t g_kh[MW],  g_kl[MW];
__device__ uint32_t g_vth[MW], g_vtl[MW];
__device__ uint32_t g_ath[MW], g_atl[MW];
__device__ uint32_t g_wqh[WW], g_wql[WW], g_wkh[WW], g_wkl[WW];
__device__ uint32_t g_wvh[WW], g_wvl[WW], g_woh[WW], g_wol[WW];
__device__ float    g_v[(size_t)MTOT*DIMC];

// ---- bf16 split helpers --------------------------------------------------
__device__ __forceinline__ uint32_t bf16_rn_bits(float x) {
    uint32_t u = __float_as_uint(x);
    return (u + 0x7FFFu + ((u >> 16) & 1u)) & 0xFFFF0000u;
}
// word = {low16: bf16(e0), high16: bf16(e1)}
__device__ __forceinline__ uint32_t pack_bf16(float e0, float e1) {
    return bf16_rn_bits(e1) | (bf16_rn_bits(e0) >> 16);
}

__device__ __forceinline__ void mma_bf16(float* d, const uint32_t* a,
                                         const uint32_t* b) {
    asm volatile(
        "mma.sync.aligned.m16n8k16.row.col.f32.bf16.bf16.f32 "
        "{%0,%1,%2,%3}, {%4,%5,%6,%7}, {%8,%9}, {%0,%1,%2,%3};"
        : "+f"(d[0]), "+f"(d[1]), "+f"(d[2]), "+f"(d[3])
        : "r"(a[0]), "r"(a[1]), "r"(a[2]), "r"(a[3]), "r"(b[0]), "r"(b[1]));
}

// Fast exp on the FMA pipe.
__device__ __forceinline__ float fast_exp(float x) {
    float z = fmaxf(x, -87.0f) * 1.4426950408889634f;
    float r = z + 12582912.0f;
    int   n = __float_as_int(r) - 0x4B400000;
    float f = z - (r - 12582912.0f);
    float p = 0.0013333558f;
    p = fmaf(p, f, 0.0096181291f);
    p = fmaf(p, f, 0.0555041087f);
    p = fmaf(p, f, 0.2402265070f);
    p = fmaf(p, f, 0.6931471806f);
    p = fmaf(p, f, 1.0f);
    return p * __int_as_float((n + 127) << 23);
}

// ===========================================================================
// Prep: fp32 array -> packed bf16 hi/lo words (one pass, boundary conversion)
// ===========================================================================
__global__ __launch_bounds__(256) void split_pack(
    const float* __restrict__ src, uint32_t* __restrict__ dh,
    uint32_t* __restrict__ dl, int n4)
{
    int i = blockIdx.x * blockDim.x + threadIdx.x;
    if (i >= n4) return;
    float4 v = ((const float4*)src)[i];
    uint32_t hx = bf16_rn_bits(v.x), hy = bf16_rn_bits(v.y);
    uint32_t hz = bf16_rn_bits(v.z), hw = bf16_rn_bits(v.w);
    ((uint2*)dh)[i] = make_uint2(hy | (hx >> 16), hw | (hz >> 16));
    ((uint2*)dl)[i] = make_uint2(
        pack_bf16(v.x - __uint_as_float(hx), v.y - __uint_as_float(hy)),
        pack_bf16(v.z - __uint_as_float(hz), v.w - __uint_as_float(hw)));
}

// ===========================================================================
// V transpose+split: g_v fp32 -> tile-transposed packed layout
//   g_vt[((b*NH+h)*(TT/64)+kt)*2048 + n*32 + t] = pack(v[2t], v[2t+1]) col n
// ===========================================================================
__global__ __launch_bounds__(128) void v_trans(
    const float* __restrict__ V, uint32_t* __restrict__ dh,
    uint32_t* __restrict__ dl)
{
    const int kt = blockIdx.x, h = blockIdx.y, b = blockIdx.z;
    const int tid = threadIdx.x;
    const int vn = tid & 63, vrb0 = tid >> 6;
    const size_t base = ((size_t)b * TT) * DIMC + (size_t)h * HD;
    const size_t tb = ((size_t)(b * NH + h) * (TT/64) + kt) * 2048;

    #pragma unroll
    for (int i = 0; i < 4; i++) {
        const int rb = vrb0 + 2*i;
        float v0[8];
        #pragma unroll
        for (int s = 0; s < 8; s++)
            v0[s] = V[base + (size_t)(kt*64 + rb*8 + s) * DIMC + vn];
        uint32_t hb[8];
        #pragma unroll
        for (int s = 0; s < 8; s++) hb[s] = bf16_rn_bits(v0[s]);
        *(uint4*)&dh[tb + vn*32 + rb*4] = make_uint4(
            hb[1] | (hb[0] >> 16), hb[3] | (hb[2] >> 16),
            hb[5] | (hb[4] >> 16), hb[7] | (hb[6] >> 16));
        *(uint4*)&dl[tb + vn*32 + rb*4] = make_uint4(
            pack_bf16(v0[0]-__uint_as_float(hb[0]), v0[1]-__uint_as_float(hb[1])),
            pack_bf16(v0[2]-__uint_as_float(hb[2]), v0[3]-__uint_as_float(hb[3])),
            pack_bf16(v0[4]-__uint_as_float(hb[4]), v0[5]-__uint_as_float(hb[5])),
            pack_bf16(v0[6]-__uint_as_float(hb[6]), v0[7]-__uint_as_float(hb[7])));
    }
}

// ===========================================================================
// Split-BF16 GEMM on pre-packed operands. C = A @ W^T.
// Epilogue: packed hi/lo out (Ch/Cl, scaled) OR fp32 out (Cf, +bias).
// ===========================================================================
#define GEMM_SMEM (4 * 128 * 20 * 4)

__global__ __launch_bounds__(256) void gemm_bf16p(
    const uint32_t* __restrict__ Ah, const uint32_t* __restrict__ Al,
    const uint32_t* __restrict__ Wh, const uint32_t* __restrict__ Wl,
    const float* __restrict__ bias, float* __restrict__ Cf,
    uint32_t* __restrict__ Ch, uint32_t* __restrict__ Cl, float oscale)
{
    extern __shared__ uint32_t gsw[];
    uint32_t* s_ah = gsw;                  // [128][20]
    uint32_t* s_al = gsw + 128*20;
    uint32_t* s_wh = gsw + 2*128*20;
    uint32_t* s_wl = gsw + 3*128*20;

    const int tid  = threadIdx.x;
    const int wid  = tid >> 5, lane = tid & 31;
    const int wm   = (wid & 3) * 32;
    const int wn   = (wid >> 2) * 64;
    const int bm   = blockIdx.y * 128, bn = blockIdx.x * 128;

    const int lrow = tid >> 3;             // 0..31
    const int wt2  = (tid & 7) * 2;        // word offset 0..14

    const int qr = lane >> 2;
    const int qc = lane & 3;

    float acc[2][8][4];
    #pragma unroll
    for (int i = 0; i < 2; i++)
        #pragma unroll
        for (int j = 0; j < 8; j++)
            #pragma unroll
            for (int t = 0; t < 4; t++) acc[i][j][t] = 0.f;

    uint2 pah[4], pal[4], pwh[4], pwl[4];
    #pragma unroll
    for (int p = 0; p < 4; p++) {
        const size_t ao = (size_t)(bm + lrow + 32*p) * 512 + wt2;
        const size_t wo = (size_t)(bn + lrow + 32*p) * 512 + wt2;
        pah[p] = *(const uint2*)&Ah[ao]; pal[p] = *(const uint2*)&Al[ao];
        pwh[p] = *(const uint2*)&Wh[wo]; pwl[p] = *(const uint2*)&Wl[wo];
    }

    for (int k0w = 0; k0w < 512; k0w += 16) {
        #pragma unroll
        for (int p = 0; p < 4; p++) {
            const int r = lrow + 32*p;
            *(uint2*)&s_ah[r*20 + wt2] = pah[p];
            *(uint2*)&s_al[r*20 + wt2] = pal[p];
            *(uint2*)&s_wh[r*20 + wt2] = pwh[p];
            *(uint2*)&s_wl[r*20 + wt2] = pwl[p];
        }
        __syncthreads();

        if (k0w + 16 < 512) {
            #pragma unroll
            for (int p = 0; p < 4; p++) {
                const size_t ao = (size_t)(bm + lrow + 32*p) * 512 + k0w + 16 + wt2;
                const size_t wo = (size_t)(bn + lrow + 32*p) * 512 + k0w + 16 + wt2;
                pah[p] = *(const uint2*)&Ah[ao]; pal[p] = *(const uint2*)&Al[ao];
                pwh[p] = *(const uint2*)&Wh[wo]; pwl[p] = *(const uint2*)&Wl[wo];
            }
        }

        #pragma unroll
        for (int k16 = 0; k16 < 2; k16++) {
            const int kw = k16*8 + qc;
            uint32_t ah[2][4], al[2][4], bh[8][2], bl[8][2];
            #pragma unroll
            for (int mf = 0; mf < 2; mf++) {
                const int m = (wm + mf*16 + qr) * 20;
                ah[mf][0] = s_ah[m + kw];
                ah[mf][1] = s_ah[m + 8*20 + kw];
                ah[mf][2] = s_ah[m + kw + 4];
                ah[mf][3] = s_ah[m + 8*20 + kw + 4];
                al[mf][0] = s_al[m + kw];
                al[mf][1] = s_al[m + 8*20 + kw];
                al[mf][2] = s_al[m + kw + 4];
                al[mf][3] = s_al[m + 8*20 + kw + 4];
            }
            #pragma unroll
            for (int nf = 0; nf < 8; nf++) {
                const int n = (wn + nf*8 + qr) * 20;
                bh[nf][0] = s_wh[n + kw];
                bh[nf][1] = s_wh[n + kw + 4];
                bl[nf][0] = s_wl[n + kw];
                bl[nf][1] = s_wl[n + kw + 4];
            }
            #pragma unroll
            for (int mf = 0; mf < 2; mf++)
                #pragma unroll
                for (int nf = 0; nf < 8; nf++) {
                    mma_bf16(acc[mf][nf], ah[mf], bh[nf]);
                    mma_bf16(acc[mf][nf], al[mf], bh[nf]);
                    mma_bf16(acc[mf][nf], ah[mf], bl[nf]);
                }
        }
        __syncthreads();
    }

    if (Cf) {
        #pragma unroll
        for (int mf = 0; mf < 2; mf++) {
            const int row = bm + wm + mf*16 + qr;
            #pragma unroll
            for (int nf = 0; nf < 8; nf++) {
                const int col = bn + wn + nf*8 + qc*2;
                float2 v0 = make_float2(acc[mf][nf][0], acc[mf][nf][1]);
                float2 v1 = make_float2(acc[mf][nf][2], acc[mf][nf][3]);
                if (bias) {
                    const float b0 = bias[col], b1 = bias[col+1];
                    v0.x += b0; v0.y += b1;
                    v1.x += b0; v1.y += b1;
                }
                *(float2*)&Cf[(size_t)row     * DIMC + col] = v0;
                *(float2*)&Cf[(size_t)(row+8) * DIMC + col] = v1;
            }
        }
    } else {
        #pragma unroll
        for (int mf = 0; mf < 2; mf++) {
            const size_t r0 = (size_t)(bm + wm + mf*16 + qr) * 512;
            const size_t r1 = r0 + 8*512;
            #pragma unroll
            for (int nf = 0; nf < 8; nf++) {
                const int cw = (bn + wn + nf*8) / 2 + qc;
                float e0 = acc[mf][nf][0] * oscale, e1 = acc[mf][nf][1] * oscale;
                float e2 = acc[mf][nf][2] * oscale, e3 = acc[mf][nf][3] * oscale;
                uint32_t h0 = bf16_rn_bits(e0), h1 = bf16_rn_bits(e1);
                uint32_t h2 = bf16_rn_bits(e2), h3 = bf16_rn_bits(e3);
                Ch[r0 + cw] = h1 | (h0 >> 16);
                Ch[r1 + cw] = h3 | (h2 >> 16);
                Cl[r0 + cw] = pack_bf16(e0 - __uint_as_float(h0),
                                        e1 - __uint_as_float(h1));
                Cl[r1 + cw] = pack_bf16(e2 - __uint_as_float(h2),
                                        e3 - __uint_as_float(h3));
            }
        }
    }
}

// ===========================================================================
// Split-BF16 causal flash attention on pre-packed Q/K/V.
// Loaders are pure copies; P stays in registers; epilogue writes packed O.
// ===========================================================================
#define SQW 36
#define WQH_ 0
#define WQL_ (64*SQW)
#define WKH_ (2*64*SQW)
#define WKL_ (3*64*SQW)
#define WVH_ (4*64*SQW)
#define WVL_ (5*64*SQW)
#define ATT_SMEM (6 * 64 * SQW * 4)   /* 55296 B */

__global__ __launch_bounds__(128) void attn_bf16(
    const uint32_t* __restrict__ qh, const uint32_t* __restrict__ ql,
    const uint32_t* __restrict__ kh, const uint32_t* __restrict__ kl,
    const uint32_t* __restrict__ vth, const uint32_t* __restrict__ vtl,
    uint32_t* __restrict__ oh, uint32_t* __restrict__ ol)
{
    extern __shared__ uint32_t smw[];
    const int tid  = threadIdx.x;
    const int w    = tid >> 5, lane = tid & 31;
    const int qr   = lane >> 2, qc = lane & 3;
    const int qt   = blockIdx.x, h = blockIdx.y, b = blockIdx.z;
    // packed row base: global row (b*TT + t), head offset h*HD/2 = h*32 words
    const size_t pbase = ((size_t)b * TT) * 512 + (size_t)h * 32;

    // ---- Q tile copy (64 rows x 32 words, hi+lo) ----
    #pragma unroll
    for (int i = 0; i < 8; i++) {
        int idx = tid + i * 128;           // 0..1023
        int r = idx >> 4, wo = (idx & 15) * 2;
        const size_t g = pbase + (size_t)(qt*64 + r) * 512 + wo;
        *(uint2*)&smw[WQH_ + r*SQW + wo] = *(const uint2*)&qh[g];
        *(uint2*)&smw[WQL_ + r*SQW + wo] = *(const uint2*)&ql[g];
    }

    float m0 = -1e30f, m1 = -1e30f, l0 = 0.f, l1 = 0.f;
    float oacc[8][4];
    #pragma unroll
    for (int nf = 0; nf < 8; nf++)
        #pragma unroll
        for (int t = 0; t < 4; t++) oacc[nf][t] = 0.f;

    const int arow = (w*16 + qr) * SQW;
    const int nkt  = qt + 1;
    const size_t vtile0 = ((size_t)(b * NH + h) * (TT/64)) * 2048;

    for (int kt = 0; kt < nkt; kt++) {
        __syncthreads();

        // ---- K tile copy ----
        #pragma unroll
        for (int i = 0; i < 8; i++) {
            int idx = tid + i * 128;
            int r = idx >> 4, wo = (idx & 15) * 2;
            const size_t g = pbase + (size_t)(kt*64 + r) * 512 + wo;
            *(uint2*)&smw[WKH_ + r*SQW + wo] = *(const uint2*)&kh[g];
            *(uint2*)&smw[WKL_ + r*SQW + wo] = *(const uint2*)&kl[g];
        }
        // ---- V tile copy (pre-transposed packed) ----
        {
            const size_t vt = vtile0 + (size_t)kt * 2048;
            #pragma unroll
            for (int i = 0; i < 4; i++) {
                int widx = tid + i * 128;      // 0..511
                int n = widx >> 3, wg = (widx & 7) * 4;
                *(uint4*)&smw[WVH_ + n*SQW + wg] = *(const uint4*)&vth[vt + n*32 + wg];
                *(uint4*)&smw[WVL_ + n*SQW + wg] = *(const uint4*)&vtl[vt + n*32 + wg];
            }
        }
        __syncthreads();

        // ---- S = Q @ K^T (3-term) ----
        float sacc[8][4];
        #pragma unroll
        for (int nf = 0; nf < 8; nf++)
            #pragma unroll
            for (int t = 0; t < 4; t++) sacc[nf][t] = 0.f;

        #pragma unroll
        for (int k16 = 0; k16 < 4; k16++) {
            const int kw = k16*8 + qc;
            uint32_t ah[4], al[4];
            ah[0] = smw[WQH_ + arow + kw];
            ah[1] = smw[WQH_ + arow + 8*SQW + kw];
            ah[2] = smw[WQH_ + arow + kw + 4];
            ah[3] = smw[WQH_ + arow + 8*SQW + kw + 4];
            al[0] = smw[WQL_ + arow + kw];
            al[1] = smw[WQL_ + arow + 8*SQW + kw];
            al[2] = smw[WQL_ + arow + kw + 4];
            al[3] = smw[WQL_ + arow + 8*SQW + kw + 4];
            #pragma unroll
            for (int nf = 0; nf < 8; nf++) {
                const int br = (nf*8 + qr) * SQW;
                uint32_t bh[2], bl[2];
                bh[0] = smw[WKH_ + br + kw];
                bh[1] = smw[WKH_ + br + kw + 4];
                bl[0] = smw[WKL_ + br + kw];
                bl[1] = smw[WKL_ + br + kw + 4];
                mma_bf16(sacc[nf], ah, bh);
                mma_bf16(sacc[nf], al, bh);
                mma_bf16(sacc[nf], ah, bl);
            }
        }

        // ---- causal mask (diagonal tile only) ----
        if (kt == qt) {
            const int r0g = qt*64 + w*16 + qr;
            #pragma unroll
            for (int nf = 0; nf < 8; nf++) {
                const int cg = kt*64 + nf*8 + qc*2;
                if (cg     > r0g)     sacc[nf][0] = -1e30f;
                if (cg + 1 > r0g)     sacc[nf][1] = -1e30f;
                if (cg     > r0g + 8) sacc[nf][2] = -1e30f;
                if (cg + 1 > r0g + 8) sacc[nf][3] = -1e30f;
            }
        }

        // ---- online softmax in registers ----
        float mx0 = -1e30f, mx1 = -1e30f;
        #pragma unroll
        for (int nf = 0; nf < 8; nf++) {
            mx0 = fmaxf(mx0, fmaxf(sacc[nf][0], sacc[nf][1]));
            mx1 = fmaxf(mx1, fmaxf(sacc[nf][2], sacc[nf][3]));
        }
        mx0 = fmaxf(mx0, __shfl_xor_sync(0xffffffffu, mx0, 1));
        mx0 = fmaxf(mx0, __shfl_xor_sync(0xffffffffu, mx0, 2));
        mx1 = fmaxf(mx1, __shfl_xor_sync(0xffffffffu, mx1, 1));
        mx1 = fmaxf(mx1, __shfl_xor_sync(0xffffffffu, mx1, 2));

        const float nm0 = fmaxf(m0, mx0), nm1 = fmaxf(m1, mx1);
        const float c0 = fast_exp(m0 - nm0), c1 = fast_exp(m1 - nm1);
        m0 = nm0; m1 = nm1;

        float rs0 = 0.f, rs1 = 0.f;
        #pragma unroll
        for (int nf = 0; nf < 8; nf++) {
            float p0 = fast_exp(sacc[nf][0] - m0);
            float p1 = fast_exp(sacc[nf][1] - m0);
            float p2 = fast_exp(sacc[nf][2] - m1);
            float p3 = fast_exp(sacc[nf][3] - m1);
            rs0 += p0 + p1; rs1 += p2 + p3;
            sacc[nf][0] = p0; sacc[nf][1] = p1;
            sacc[nf][2] = p2; sacc[nf][3] = p3;
        }
        rs0 += __shfl_xor_sync(0xffffffffu, rs0, 1);
        rs0 += __shfl_xor_sync(0xffffffffu, rs0, 2);
        rs1 += __shfl_xor_sync(0xffffffffu, rs1, 1);
        rs1 += __shfl_xor_sync(0xffffffffu, rs1, 2);
        l0 = l0 * c0 + rs0;
        l1 = l1 * c1 + rs1;
        #pragma unroll
        for (int nf = 0; nf < 8; nf++) {
            oacc[nf][0] *= c0; oacc[nf][1] *= c0;
            oacc[nf][2] *= c1; oacc[nf][3] *= c1;
        }

        // ---- O += P @ V : same-lane C-frag -> A-frag pack, 3-term ----
        #pragma unroll
        for (int k16 = 0; k16 < 4; k16++) {
            const int g0 = 2*k16, g1 = 2*k16 + 1;
            uint32_t aph[4], apl[4];
            {
                uint32_t h00 = bf16_rn_bits(sacc[g0][0]);
                uint32_t h01 = bf16_rn_bits(sacc[g0][1]);
                uint32_t h02 = bf16_rn_bits(sacc[g0][2]);
                uint32_t h03 = bf16_rn_bits(sacc[g0][3]);
                uint32_t h10 = bf16_rn_bits(sacc[g1][0]);
                uint32_t h11 = bf16_rn_bits(sacc[g1][1]);
                uint32_t h12 = bf16_rn_bits(sacc[g1][2]);
                uint32_t h13 = bf16_rn_bits(sacc[g1][3]);
                aph[0] = h01 | (h00 >> 16);
                aph[1] = h03 | (h02 >> 16);
                aph[2] = h11 | (h10 >> 16);
                aph[3] = h13 | (h12 >> 16);
                apl[0] = pack_bf16(sacc[g0][0] - __uint_as_float(h00),
                                   sacc[g0][1] - __uint_as_float(h01));
                apl[1] = pack_bf16(sacc[g0][2] - __uint_as_float(h02),
                                   sacc[g0][3] - __uint_as_float(h03));
                apl[2] = pack_bf16(sacc[g1][0] - __uint_as_float(h10),
                                   sacc[g1][1] - __uint_as_float(h11));
                apl[3] = pack_bf16(sacc[g1][2] - __uint_as_float(h12),
                                   sacc[g1][3] - __uint_as_float(h13));
            }
            const int kw = k16*8 + qc;
            #pragma unroll
            for (int nf = 0; nf < 8; nf++) {
                const int bn_ = (nf*8 + qr) * SQW;
                uint32_t bh[2], bl[2];
                bh[0] = smw[WVH_ + bn_ + kw];
                bh[1] = smw[WVH_ + bn_ + kw + 4];
                bl[0] = smw[WVL_ + bn_ + kw];
                bl[1] = smw[WVL_ + bn_ + kw + 4];
                mma_bf16(oacc[nf], aph, bh);
                mma_bf16(oacc[nf], apl, bh);
                mma_bf16(oacc[nf], aph, bl);
            }
        }
    }

    // ---- normalize + write packed O ----
    const float inv0 = 1.f / l0, inv1 = 1.f / l1;
    const size_t r0 = pbase + (size_t)(qt*64 + w*16 + qr) * 512;
    const size_t r1 = r0 + 8*512;
    #pragma unroll
    for (int nf = 0; nf < 8; nf++) {
        const int cw = nf*4 + qc;
        float e0 = oacc[nf][0]*inv0, e1 = oacc[nf][1]*inv0;
        float e2 = oacc[nf][2]*inv1, e3 = oacc[nf][3]*inv1;
        uint32_t h0 = bf16_rn_bits(e0), h1 = bf16_rn_bits(e1);
        uint32_t h2 = bf16_rn_bits(e2), h3 = bf16_rn_bits(e3);
        oh[r0 + cw] = h1 | (h0 >> 16);
        oh[r1 + cw] = h3 | (h2 >> 16);
        ol[r0 + cw] = pack_bf16(e0 - __uint_as_float(h0), e1 - __uint_as_float(h1));
        ol[r1 + cw] = pack_bf16(e2 - __uint_as_float(h2), e3 - __uint_as_float(h3));
    }
}

// ---------------------------------------------------------------------------
extern "C" void kernel_launch(void* const* d_in, const int* in_sizes, int n_in,
                              void* d_out, int out_size)
{
    const float* x  = (const float*)d_in[0];
    const float* Wq = (const float*)d_in[2];
    const float* Wk = (const float*)d_in[3];
    const float* Wv = (const float*)d_in[4];
    const float* Wo = (const float*)d_in[5];
    const float* bo = (const float*)d_in[6];
    float* out = (float*)d_out;

    uint32_t *xh,*xl,*qh,*ql,*kh,*kl,*vth,*vtl,*ath,*atl;
    uint32_t *wqh,*wql,*wkh,*wkl,*wvh,*wvl,*woh,*wol;
    float *v;
    cudaGetSymbolAddress((void**)&xh, g_xh);   cudaGetSymbolAddress((void**)&xl, g_xl);
    cudaGetSymbolAddress((void**)&qh, g_qh);   cudaGetSymbolAddress((void**)&ql, g_ql);
    cudaGetSymbolAddress((void**)&kh, g_kh);   cudaGetSymbolAddress((void**)&kl, g_kl);
    cudaGetSymbolAddress((void**)&vth, g_vth); cudaGetSymbolAddress((void**)&vtl, g_vtl);
    cudaGetSymbolAddress((void**)&ath, g_ath); cudaGetSymbolAddress((void**)&atl, g_atl);
    cudaGetSymbolAddress((void**)&wqh, g_wqh); cudaGetSymbolAddress((void**)&wql, g_wql);
    cudaGetSymbolAddress((void**)&wkh, g_wkh); cudaGetSymbolAddress((void**)&wkl, g_wkl);
    cudaGetSymbolAddress((void**)&wvh, g_wvh); cudaGetSymbolAddress((void**)&wvl, g_wvl);
    cudaGetSymbolAddress((void**)&woh, g_woh); cudaGetSymbolAddress((void**)&wol, g_wol);
    cudaGetSymbolAddress((void**)&v, g_v);

    cudaFuncSetAttribute(gemm_bf16p,
                         cudaFuncAttributeMaxDynamicSharedMemorySize, GEMM_SMEM);
    cudaFuncSetAttribute(attn_bf16,
                         cudaFuncAttributeMaxDynamicSharedMemorySize, ATT_SMEM);

    // Prep: split/pack x and weights (boundary conversion, once per call)
    const int n4x = MTOT*DIMC/4, n4w = DIMC*DIMC/4;
    split_pack<<<(n4x+255)/256, 256>>>(x,  xh,  xl,  n4x);
    split_pack<<<(n4w+255)/256, 256>>>(Wq, wqh, wql, n4w);
    split_pack<<<(n4w+255)/256, 256>>>(Wk, wkh, wkl, n4w);
    split_pack<<<(n4w+255)/256, 256>>>(Wv, wvh, wvl, n4w);
    split_pack<<<(n4w+255)/256, 256>>>(Wo, woh, wol, n4w);

    dim3 gb(DIMC/128, MTOT/128);   // (8, 64)
    gemm_bf16p<<<gb, 256, GEMM_SMEM>>>(xh, xl, wqh, wql, nullptr,
                                       nullptr, qh, ql, 0.125f);
    gemm_bf16p<<<gb, 256, GEMM_SMEM>>>(xh, xl, wkh, wkl, nullptr,
                                       nullptr, kh, kl, 1.0f);
    gemm_bf16p<<<gb, 256, GEMM_SMEM>>>(xh, xl, wvh, wvl, nullptr,
                                       v, nullptr, nullptr, 1.0f);

    dim3 gv(TT/64, NH, BB);
    v_trans<<<gv, 128>>>(v, vth, vtl);

    dim3 ga(TT/64, NH, BB);        // (32,16,4)
    attn_bf16<<<ga, 128, ATT_SMEM>>>(qh, ql, kh, kl, vth, vtl, ath, atl);

    gemm_bf16p<<<gb, 256, GEMM_SMEM>>>(ath, atl, woh, wol, bo,
                                       out, nullptr, nullptr, 1.0f);
}